// round 2
// baseline (speedup 1.0000x reference)
#include <cuda_runtime.h>
#include <math.h>

#define LSEQ 64
#define DDIM 64
#define NH   8
#define PCNT 62

// ---------------- scratch (static __device__, no allocation) ----------------
__device__ float g_qkv[4096 * 24 * 64];          // [v][jh][d], jh: 0-7 q, 8-15 k, 16-23 v
__device__ float g_M[64 * 64 * 64];              // [l][m'][m]
__device__ float g_S[2048 * 8 * 64 * 64];        // [b*H+h][l][m] : sim -> attn (in place)
__device__ float g_ln[2048 * 8 * 64 * 64];       // [b][h][l][d]  : layernormed attention out
__device__ float g_word[2048 * 2048];            // [b][f]

// ---------------- K0a: qkv table = W_emb @ W_qkv^T ----------------
__global__ __launch_bounds__(256) void k_qkv(const float* __restrict__ W_emb,
                                             const float* __restrict__ W_qkv) {
    __shared__ float As[64][65];   // emb rows [v_local][k]
    __shared__ float Bs[64][65];   // W_qkv transposed: Bs[k][r_local]
    int v0 = blockIdx.y * 64, r0 = blockIdx.x * 64;
    int t = threadIdx.x;
    for (int i = t; i < 4096; i += 256) {
        int row = i >> 6, col = i & 63;
        As[row][col] = W_emb[(size_t)(v0 + row) * 64 + col];
        Bs[col][row] = W_qkv[(size_t)(r0 + row) * 64 + col];
    }
    __syncthreads();
    int i = t >> 2, j = t & 3;
    float acc[16];
#pragma unroll
    for (int c = 0; c < 16; c++) acc[c] = 0.f;
#pragma unroll
    for (int k = 0; k < 64; k++) {
        float a = As[i][k];
#pragma unroll
        for (int c = 0; c < 16; c++) acc[c] += a * Bs[k][j + 4 * c];
    }
#pragma unroll
    for (int c = 0; c < 16; c++)
        g_qkv[(size_t)(v0 + i) * 1536 + r0 + j + 4 * c] = acc[c];
}

// ---------------- K0b: fused position table ----------------
// M[l][m'][m] = (1/62) * sum_{i=0..30} [ W_pos[i][m']*cos(a) + W_pos[i+31][m']*sin(a) ]
// a = (i+1)*(m-l)*2*pi/63
__global__ __launch_bounds__(256) void k_mtab(const float* __restrict__ W_pos) {
    int idx = blockIdx.x * 256 + threadIdx.x;     // l*4096 + mp*64 + m
    int l = idx >> 12, mp = (idx >> 6) & 63, m = idx & 63;
    float base = (float)(m - l) * (6.283185307179586f / 63.0f);
    float acc = 0.f;
    for (int i = 0; i < 31; i++) {
        float s, c;
        sincosf((float)(i + 1) * base, &s, &c);
        acc += W_pos[i * 64 + mp] * c + W_pos[(i + 31) * 64 + mp] * s;
    }
    g_M[idx] = acc * (1.0f / 62.0f);
}

// ---------------- K1: sim = Q K^T / sqrt(D), key-pad masked ----------------
__global__ __launch_bounds__(256) void k_sim(const int* __restrict__ inputs) {
    __shared__ float Qs[64][65];
    __shared__ float Ks[64][65];
    __shared__ int toks[64];
    int h = blockIdx.x, b = blockIdx.y, t = threadIdx.x;
    if (t < 64) toks[t] = inputs[b * 64 + t];
    __syncthreads();
    for (int i = t; i < 4096; i += 256) {
        int m = i >> 6, d = i & 63;
        size_t base = (size_t)toks[m] * 1536;
        Qs[m][d] = g_qkv[base + h * 64 + d];
        Ks[m][d] = g_qkv[base + (NH + h) * 64 + d];
    }
    __syncthreads();
    int l = t >> 2, j = t & 3;
    float acc[16];
#pragma unroll
    for (int c = 0; c < 16; c++) acc[c] = 0.f;
#pragma unroll
    for (int k = 0; k < 64; k++) {
        float q = Qs[l][k];
#pragma unroll
        for (int c = 0; c < 16; c++) acc[c] += q * Ks[j + 4 * c][k];
    }
    size_t off = ((size_t)(b * NH + h) * 64 + l) * 64;
#pragma unroll
    for (int c = 0; c < 16; c++) {
        int m = j + 4 * c;
        float s = acc[c] * 0.125f;
        if (toks[m] == 0) s = -1e9f;
        g_S[off + m] = s;
    }
}

// ---------------- K2: pos bias (via M[l]) + softmax, in place on g_S ----------------
__global__ __launch_bounds__(256) void k_pos_softmax() {
    __shared__ float Msm[64][64];      // [m'][m]
    __shared__ float srow[8][64];
    int l = blockIdx.x;
    int t = threadIdx.x, w = t >> 5, lane = t & 31;
    for (int i = t; i < 4096; i += 256) Msm[i >> 6][i & 63] = g_M[l * 4096 + i];
    __syncthreads();
    int rowbase = blockIdx.y * 64 + w * 8;
    for (int r = 0; r < 8; r++) {
        size_t off = ((size_t)(rowbase + r) * 64 + l) * 64;
        float s0 = g_S[off + lane];
        float s1 = g_S[off + 32 + lane];
        srow[w][lane] = s0;
        srow[w][32 + lane] = s1;
        __syncwarp();
        float b0 = 0.f, b1 = 0.f;
#pragma unroll
        for (int mp = 0; mp < 64; mp++) {
            float sv = srow[w][mp];
            sv = (sv > -1e8f) ? sv : 0.f;
            b0 += sv * Msm[mp][lane];
            b1 += sv * Msm[mp][32 + lane];
        }
        float z0 = s0 + b0, z1 = s1 + b1;
        float mx = fmaxf(z0, z1);
        for (int d = 16; d > 0; d >>= 1) mx = fmaxf(mx, __shfl_xor_sync(0xffffffffu, mx, d));
        float e0 = __expf(z0 - mx), e1 = __expf(z1 - mx);
        float sm = e0 + e1;
        for (int d = 16; d > 0; d >>= 1) sm += __shfl_xor_sync(0xffffffffu, sm, d);
        float inv = 1.0f / sm;
        g_S[off + lane] = e0 * inv;
        g_S[off + 32 + lane] = e1 * inv;
        __syncwarp();
    }
}

// ---------------- K3: out = attn @ V, then layernorm over D ----------------
__global__ __launch_bounds__(256) void k_av_ln(const int* __restrict__ inputs,
                                               const float* __restrict__ ln_g,
                                               const float* __restrict__ ln_b) {
    __shared__ float Asm[64][65];   // attn [l][m]
    __shared__ float Vsm[64][65];   // v    [m][d]
    __shared__ int toks[64];
    __shared__ float gam[64], bet[64];
    int h = blockIdx.x, b = blockIdx.y, t = threadIdx.x;
    if (t < 64) { toks[t] = inputs[b * 64 + t]; gam[t] = ln_g[t]; bet[t] = ln_b[t]; }
    __syncthreads();
    size_t soff = (size_t)(b * NH + h) * 4096;
    for (int i = t; i < 4096; i += 256) {
        int m = i >> 6, d = i & 63;
        Asm[m][d] = g_S[soff + i];
        Vsm[m][d] = g_qkv[(size_t)toks[m] * 1536 + (2 * NH + h) * 64 + d];
    }
    __syncthreads();
    int l = t >> 2, j = t & 3;
    float acc[16];
#pragma unroll
    for (int c = 0; c < 16; c++) acc[c] = 0.f;
#pragma unroll
    for (int m = 0; m < 64; m++) {
        float a = Asm[l][m];
#pragma unroll
        for (int c = 0; c < 16; c++) acc[c] += a * Vsm[m][j + 4 * c];
    }
    float s = 0.f, sq = 0.f;
#pragma unroll
    for (int c = 0; c < 16; c++) { s += acc[c]; sq += acc[c] * acc[c]; }
    s += __shfl_xor_sync(0xffffffffu, s, 1);
    s += __shfl_xor_sync(0xffffffffu, s, 2);
    sq += __shfl_xor_sync(0xffffffffu, sq, 1);
    sq += __shfl_xor_sync(0xffffffffu, sq, 2);
    float mu = s * (1.0f / 64.0f);
    float var = sq * (1.0f / 64.0f) - mu * mu;
    float inv = rsqrtf(var + 1e-5f);
    size_t lo = (size_t)(b * NH + h) * 4096 + (size_t)l * 64;   // layout [b][h][l][d]
#pragma unroll
    for (int c = 0; c < 16; c++) {
        int d = j + 4 * c;
        g_ln[lo + d] = (acc[c] - mu) * inv * gam[d] + bet[d];
    }
}

// ---------------- K4: MLP + masked word mean (W2 pulled out of the l-sum) ----------------
__global__ __launch_bounds__(256) void k_mlp(const int* __restrict__ inputs,
                                             const float* __restrict__ W1,
                                             const float* __restrict__ b1,
                                             const float* __restrict__ W2,
                                             const float* __restrict__ b2) {
    __shared__ float W1s[64][8];
    __shared__ float b1s[64];
    __shared__ float W2s[32][64];
    __shared__ float b2s[32];
    __shared__ float part[4][2048];
    __shared__ int toks[64];
    int b = blockIdx.x, t = threadIdx.x;
    if (t < 64) { toks[t] = inputs[b * 64 + t]; b1s[t] = b1[t]; }
    if (t < 32) b2s[t] = b2[t];
    for (int i = t; i < 512; i += 256) W1s[i >> 3][i & 7] = W1[i];
    for (int i = t; i < 2048; i += 256) W2s[i >> 6][i & 63] = W2[i];
    __syncthreads();
    float cnt = 0.f;
    for (int m = 0; m < 64; m++) cnt += (toks[m] != 0) ? 1.f : 0.f;

    int d = t & 63, lg = t >> 6;
    float hs[64];
#pragma unroll
    for (int o = 0; o < 64; o++) hs[o] = 0.f;
    for (int li = 0; li < 16; li++) {
        int l = lg * 16 + li;
        if (toks[l] == 0) continue;
        float ft[8];
#pragma unroll
        for (int hh = 0; hh < 8; hh++)
            ft[hh] = g_ln[(((size_t)b * 8 + hh) * 64 + l) * 64 + d];
#pragma unroll
        for (int o = 0; o < 64; o++) {
            float v = b1s[o];
#pragma unroll
            for (int hh = 0; hh < 8; hh++) v += W1s[o][hh] * ft[hh];
            hs[o] += fmaxf(v, 0.f);
        }
    }
    float acc[32];
#pragma unroll
    for (int p = 0; p < 32; p++) acc[p] = 0.f;
#pragma unroll
    for (int o = 0; o < 64; o++) {
        float hv = hs[o];
#pragma unroll
        for (int p = 0; p < 32; p++) acc[p] += W2s[p][o] * hv;
    }
#pragma unroll
    for (int p = 0; p < 32; p++) part[lg][d * 32 + p] = acc[p];
    __syncthreads();
    float invc = 1.0f / cnt;
    for (int f = t; f < 2048; f += 256) {
        float w = part[0][f] + part[1][f] + part[2][f] + part[3][f];
        g_word[(size_t)b * 2048 + f] = w * invc + b2s[f & 31];
    }
}

// ---------------- K5: name mean over n_words ----------------
__global__ __launch_bounds__(256) void k_name(float* __restrict__ out, int n_words, int total) {
    int idx = blockIdx.x * 256 + threadIdx.x;
    if (idx >= total) return;
    int g = idx >> 11, f = idx & 2047;
    float s = 0.f;
    for (int w = 0; w < n_words; w++)
        s += g_word[(size_t)(g * n_words + w) * 2048 + f];
    out[idx] = s / (float)n_words;
}

// ---------------- launch ----------------
extern "C" void kernel_launch(void* const* d_in, const int* in_sizes, int n_in,
                              void* d_out, int out_size) {
    const int* inputs  = (const int*)d_in[0];
    const float* W_emb = (const float*)d_in[1];
    const float* W_qkv = (const float*)d_in[2];
    const float* W_pos = (const float*)d_in[3];
    const float* ln_g  = (const float*)d_in[4];
    const float* ln_b  = (const float*)d_in[5];
    const float* W1    = (const float*)d_in[6];
    const float* b1    = (const float*)d_in[7];
    const float* W2    = (const float*)d_in[8];
    const float* b2    = (const float*)d_in[9];

    int B = in_sizes[0] / 64;                         // 2048
    int V = in_sizes[1] / 64;                         // 4096
    int n_words = (int)(((long long)B * 2048) / out_size);

    k_qkv<<<dim3(24, V / 64), 256>>>(W_emb, W_qkv);
    k_mtab<<<1024, 256>>>(W_pos);
    k_sim<<<dim3(NH, B), 256>>>(inputs);
    k_pos_softmax<<<dim3(64, (B * NH) / 64), 256>>>();
    k_av_ln<<<dim3(NH, B), 256>>>(inputs, ln_g, ln_b);
    k_mlp<<<B, 256>>>(inputs, W1, b1, W2, b2);
    k_name<<<(out_size + 255) / 256, 256>>>((float*)d_out, n_words, out_size);
}

// round 3
// speedup vs baseline: 2.3797x; 2.3797x over previous
#include <cuda_runtime.h>
#include <math.h>

#define NH 8

// ---------------- scratch (static __device__, no allocation) ----------------
__device__ float g_qkv[4096 * 24 * 64];          // [v][jh][d], jh: 0-7 q, 8-15 k, 16-23 v
__device__ float g_M[64 * 64 * 64];              // [l][m'][m]
__device__ float g_S[2048 * 8 * 64 * 64];        // [b*H+h][l][m] : sim -> attn (in place)
__device__ float g_ln[2048 * 8 * 64 * 64];       // [b][h][l][d]
__device__ float g_word[2048 * 2048];            // [b][f]

// 16 FMA from two float4s into acc[4][4]
#define TILE_FMA(acc, a, b)                                        \
    do {                                                           \
        float av_[4] = {a.x, a.y, a.z, a.w};                       \
        float bv_[4] = {b.x, b.y, b.z, b.w};                       \
        _Pragma("unroll") for (int ii_ = 0; ii_ < 4; ii_++)        \
        _Pragma("unroll") for (int jj_ = 0; jj_ < 4; jj_++)        \
            acc[ii_][jj_] += av_[ii_] * bv_[jj_];                  \
    } while (0)

// ---------------- K0a: qkv table = W_emb @ W_qkv^T ----------------
__global__ __launch_bounds__(256) void k_qkv(const float* __restrict__ W_emb,
                                             const float* __restrict__ W_qkv) {
    __shared__ float At[64][68];   // emb^T : At[k][v_local]
    __shared__ float Bs[64][68];   // Wqkv^T: Bs[k][r_local]
    int v0 = blockIdx.y * 64, r0 = blockIdx.x * 64;
    int t = threadIdx.x;
    for (int i = t; i < 4096; i += 256) {
        int row = i >> 6, col = i & 63;
        At[col][row] = W_emb[(size_t)(v0 + row) * 64 + col];
        Bs[col][row] = W_qkv[(size_t)(r0 + row) * 64 + col];
    }
    __syncthreads();
    int tx = t & 15, ty = t >> 4;
    float acc[4][4] = {};
#pragma unroll
    for (int k = 0; k < 64; k++) {
        float4 a = *(const float4*)&At[k][4 * ty];
        float4 b = *(const float4*)&Bs[k][4 * tx];
        TILE_FMA(acc, a, b);
    }
#pragma unroll
    for (int i = 0; i < 4; i++) {
        float4 v = make_float4(acc[i][0], acc[i][1], acc[i][2], acc[i][3]);
        *(float4*)&g_qkv[(size_t)(v0 + 4 * ty + i) * 1536 + r0 + 4 * tx] = v;
    }
}

// ---------------- K0b: fused position table ----------------
__global__ __launch_bounds__(256) void k_mtab(const float* __restrict__ W_pos) {
    int idx = blockIdx.x * 256 + threadIdx.x;     // l*4096 + mp*64 + m
    int l = idx >> 12, mp = (idx >> 6) & 63, m = idx & 63;
    float base = (float)(m - l) * (6.283185307179586f / 63.0f);
    float acc = 0.f;
    for (int i = 0; i < 31; i++) {
        float s, c;
        sincosf((float)(i + 1) * base, &s, &c);
        acc += W_pos[i * 64 + mp] * c + W_pos[(i + 31) * 64 + mp] * s;
    }
    g_M[idx] = acc * (1.0f / 62.0f);
}

// ---------------- K1: sim = Q K^T / sqrt(D), key-pad masked ----------------
__global__ __launch_bounds__(256) void k_sim(const int* __restrict__ inputs) {
    __shared__ float Qt[64][68];   // Q^T: Qt[d][l]
    __shared__ float Kt[64][68];   // K^T: Kt[d][m]
    __shared__ int toks[64];
    int h = blockIdx.x, b = blockIdx.y, t = threadIdx.x;
    if (t < 64) toks[t] = inputs[b * 64 + t];
    __syncthreads();
    for (int i = t; i < 4096; i += 256) {
        int m = i >> 6, d = i & 63;
        size_t base = (size_t)toks[m] * 1536 + (size_t)h * 64 + d;
        Qt[d][m] = g_qkv[base];
        Kt[d][m] = g_qkv[base + 512];     // (NH+h)*64 = h*64 + 512
    }
    __syncthreads();
    int tx = t & 15, ty = t >> 4;
    float acc[4][4] = {};
#pragma unroll
    for (int k = 0; k < 64; k++) {
        float4 a = *(const float4*)&Qt[k][4 * ty];
        float4 b = *(const float4*)&Kt[k][4 * tx];
        TILE_FMA(acc, a, b);
    }
    int msk[4];
#pragma unroll
    for (int j = 0; j < 4; j++) msk[j] = (toks[4 * tx + j] == 0);
    size_t off = (size_t)(b * NH + h) * 4096;
#pragma unroll
    for (int i = 0; i < 4; i++) {
        float4 v;
        v.x = msk[0] ? -1e9f : acc[i][0] * 0.125f;
        v.y = msk[1] ? -1e9f : acc[i][1] * 0.125f;
        v.z = msk[2] ? -1e9f : acc[i][2] * 0.125f;
        v.w = msk[3] ? -1e9f : acc[i][3] * 0.125f;
        *(float4*)&g_S[off + (size_t)(4 * ty + i) * 64 + 4 * tx] = v;
    }
}

// ---------------- K2: pos bias (via M[l]) + softmax, in place on g_S ----------------
__global__ __launch_bounds__(256) void k_pos_softmax() {
    __shared__ float Ms[64][64];   // M[l]: [m'][m]  (natural, aligned)
    __shared__ float Sct[64][68];  // clipped S^T: Sct[m'][r]
    __shared__ float Ss[64][68];   // raw S: Ss[r][m]
    int l = blockIdx.x, r0 = blockIdx.y * 64, t = threadIdx.x;
    for (int i = t; i < 1024; i += 256)
        ((float4*)&Ms[0][0])[i] = ((const float4*)(g_M + (size_t)l * 4096))[i];
    for (int i = t; i < 4096; i += 256) {
        int r = i >> 6, m = i & 63;
        float s = g_S[((size_t)(r0 + r) * 64 + l) * 64 + m];
        Ss[r][m] = s;
        Sct[m][r] = (s > -1e8f) ? s : 0.f;
    }
    __syncthreads();
    int tx = t & 15, ty = t >> 4;
    float acc[4][4] = {};
#pragma unroll
    for (int k = 0; k < 64; k++) {
        float4 a = *(const float4*)&Sct[k][4 * ty];
        float4 b = *(const float4*)&Ms[k][4 * tx];
        TILE_FMA(acc, a, b);
    }
#pragma unroll
    for (int i = 0; i < 4; i++) {
        int r = 4 * ty + i;
        float z[4];
#pragma unroll
        for (int j = 0; j < 4; j++) z[j] = Ss[r][4 * tx + j] + acc[i][j];
        float mx = fmaxf(fmaxf(z[0], z[1]), fmaxf(z[2], z[3]));
#pragma unroll
        for (int d = 1; d < 16; d <<= 1)
            mx = fmaxf(mx, __shfl_xor_sync(0xffffffffu, mx, d));
        float e[4], sm = 0.f;
#pragma unroll
        for (int j = 0; j < 4; j++) { e[j] = __expf(z[j] - mx); sm += e[j]; }
#pragma unroll
        for (int d = 1; d < 16; d <<= 1)
            sm += __shfl_xor_sync(0xffffffffu, sm, d);
        float inv = 1.0f / sm;
        float4 v = make_float4(e[0] * inv, e[1] * inv, e[2] * inv, e[3] * inv);
        *(float4*)&g_S[((size_t)(r0 + r) * 64 + l) * 64 + 4 * tx] = v;
    }
}

// ---------------- K3: out = attn @ V, then layernorm over D ----------------
__global__ __launch_bounds__(256) void k_av_ln(const int* __restrict__ inputs,
                                               const float* __restrict__ ln_g,
                                               const float* __restrict__ ln_b) {
    __shared__ float Att[64][68];  // attn^T: Att[m][l]
    __shared__ float Vs[64][64];   // V: [m][d]  (natural, aligned)
    __shared__ int toks[64];
    __shared__ float gam[64], bet[64];
    int h = blockIdx.x, b = blockIdx.y, t = threadIdx.x;
    if (t < 64) { toks[t] = inputs[b * 64 + t]; gam[t] = ln_g[t]; bet[t] = ln_b[t]; }
    __syncthreads();
    size_t soff = (size_t)(b * NH + h) * 4096;
    for (int i = t; i < 4096; i += 256) {
        int row = i >> 6, col = i & 63;
        Att[col][row] = g_S[soff + i];                                  // row=l, col=m
        Vs[row][col] = g_qkv[(size_t)toks[row] * 1536 + (size_t)(2 * NH + h) * 64 + col];
    }
    __syncthreads();
    int tx = t & 15, ty = t >> 4;
    float acc[4][4] = {};
#pragma unroll
    for (int k = 0; k < 64; k++) {
        float4 a = *(const float4*)&Att[k][4 * ty];
        float4 b = *(const float4*)&Vs[k][4 * tx];
        TILE_FMA(acc, a, b);
    }
    size_t lo = (size_t)(b * NH + h) * 4096;
#pragma unroll
    for (int i = 0; i < 4; i++) {
        int l = 4 * ty + i;
        float s = acc[i][0] + acc[i][1] + acc[i][2] + acc[i][3];
        float sq = acc[i][0] * acc[i][0] + acc[i][1] * acc[i][1]
                 + acc[i][2] * acc[i][2] + acc[i][3] * acc[i][3];
#pragma unroll
        for (int d = 1; d < 16; d <<= 1) {
            s  += __shfl_xor_sync(0xffffffffu, s, d);
            sq += __shfl_xor_sync(0xffffffffu, sq, d);
        }
        float mu = s * (1.0f / 64.0f);
        float var = sq * (1.0f / 64.0f) - mu * mu;
        float inv = rsqrtf(var + 1e-5f);
        float4 v;
        v.x = (acc[i][0] - mu) * inv * gam[4 * tx + 0] + bet[4 * tx + 0];
        v.y = (acc[i][1] - mu) * inv * gam[4 * tx + 1] + bet[4 * tx + 1];
        v.z = (acc[i][2] - mu) * inv * gam[4 * tx + 2] + bet[4 * tx + 2];
        v.w = (acc[i][3] - mu) * inv * gam[4 * tx + 3] + bet[4 * tx + 3];
        *(float4*)&g_ln[lo + (size_t)l * 64 + 4 * tx] = v;
    }
}

// ---------------- K4: MLP + masked word mean (W2 pulled out of the l-sum) ----------------
__global__ __launch_bounds__(256) void k_mlp(const int* __restrict__ inputs,
                                             const float* __restrict__ W1,
                                             const float* __restrict__ b1,
                                             const float* __restrict__ W2,
                                             const float* __restrict__ b2) {
    __shared__ float W1s[512];        // [o][h], rows of 8 (32B aligned)
    __shared__ float b1s[64];
    __shared__ float W2t[64][32];     // W2^T: W2t[o][p], rows 128B aligned
    __shared__ float b2s[32];
    __shared__ float part[4][2048];
    __shared__ int toks[64];
    int b = blockIdx.x, t = threadIdx.x;
    if (t < 64) { toks[t] = inputs[b * 64 + t]; b1s[t] = b1[t]; }
    if (t < 32) b2s[t] = b2[t];
    for (int i = t; i < 512; i += 256) W1s[i] = W1[i];
    for (int i = t; i < 2048; i += 256) {
        int o = i >> 5, p = i & 31;
        W2t[o][p] = W2[p * 64 + o];
    }
    __syncthreads();
    float cnt = 0.f;
    for (int m = 0; m < 64; m++) cnt += (toks[m] != 0) ? 1.f : 0.f;

    int d = t & 63, lg = t >> 6;
    float hs[64];
#pragma unroll
    for (int o = 0; o < 64; o++) hs[o] = 0.f;
    for (int li = 0; li < 16; li++) {
        int l = lg * 16 + li;
        if (toks[l] == 0) continue;
        float ft[8];
#pragma unroll
        for (int hh = 0; hh < 8; hh++)
            ft[hh] = g_ln[(((size_t)b * 8 + hh) * 64 + l) * 64 + d];
#pragma unroll
        for (int o = 0; o < 64; o++) {
            float4 wa = *(const float4*)&W1s[o * 8];
            float4 wb = *(const float4*)&W1s[o * 8 + 4];
            float v = b1s[o]
                    + wa.x * ft[0] + wa.y * ft[1] + wa.z * ft[2] + wa.w * ft[3]
                    + wb.x * ft[4] + wb.y * ft[5] + wb.z * ft[6] + wb.w * ft[7];
            hs[o] += fmaxf(v, 0.f);
        }
    }
    float acc[32];
#pragma unroll
    for (int p = 0; p < 32; p++) acc[p] = 0.f;
#pragma unroll
    for (int o = 0; o < 64; o++) {
        float hv = hs[o];
#pragma unroll
        for (int q = 0; q < 8; q++) {
            float4 w = *(const float4*)&W2t[o][4 * q];
            acc[4 * q + 0] += w.x * hv;
            acc[4 * q + 1] += w.y * hv;
            acc[4 * q + 2] += w.z * hv;
            acc[4 * q + 3] += w.w * hv;
        }
    }
#pragma unroll
    for (int p = 0; p < 32; p++) part[lg][d * 32 + p] = acc[p];
    __syncthreads();
    float invc = 1.0f / cnt;
    for (int f = t; f < 2048; f += 256) {
        float w = part[0][f] + part[1][f] + part[2][f] + part[3][f];
        g_word[(size_t)b * 2048 + f] = w * invc + b2s[f & 31];
    }
}

// ---------------- K5: name mean over n_words ----------------
__global__ __launch_bounds__(256) void k_name(float* __restrict__ out, int n_words, int total) {
    int idx = blockIdx.x * 256 + threadIdx.x;
    if (idx >= total) return;
    int g = idx >> 11, f = idx & 2047;
    float s = 0.f;
    for (int w = 0; w < n_words; w++)
        s += g_word[(size_t)(g * n_words + w) * 2048 + f];
    out[idx] = s / (float)n_words;
}

// ---------------- launch ----------------
extern "C" void kernel_launch(void* const* d_in, const int* in_sizes, int n_in,
                              void* d_out, int out_size) {
    const int* inputs  = (const int*)d_in[0];
    const float* W_emb = (const float*)d_in[1];
    const float* W_qkv = (const float*)d_in[2];
    const float* W_pos = (const float*)d_in[3];
    const float* ln_g  = (const float*)d_in[4];
    const float* ln_b  = (const float*)d_in[5];
    const float* W1    = (const float*)d_in[6];
    const float* b1    = (const float*)d_in[7];
    const float* W2    = (const float*)d_in[8];
    const float* b2    = (const float*)d_in[9];

    int B = in_sizes[0] / 64;                         // 2048
    int V = in_sizes[1] / 64;                         // 4096
    int n_words = (int)(((long long)B * 2048) / out_size);

    k_qkv<<<dim3(24, V / 64), 256>>>(W_emb, W_qkv);
    k_mtab<<<1024, 256>>>(W_pos);
    k_sim<<<dim3(NH, B), 256>>>(inputs);
    k_pos_softmax<<<dim3(64, (B * NH) / 64), 256>>>();
    k_av_ln<<<dim3(NH, B), 256>>>(inputs, ln_g, ln_b);
    k_mlp<<<B, 256>>>(inputs, W1, b1, W2, b2);
    k_name<<<(out_size + 255) / 256, 256>>>((float*)d_out, n_words, out_size);
}

// round 4
// speedup vs baseline: 2.4636x; 1.0353x over previous
#include <cuda_runtime.h>
#include <math.h>

#define NH 8

// ---------------- scratch (static __device__, no allocation) ----------------
__device__ float g_qkv[4096 * 24 * 64];          // [v][jh][d], jh: 0-7 q, 8-15 k, 16-23 v
__device__ float g_M[64 * 64 * 64];              // [l][m'][m]
__device__ float g_S[2048 * 8 * 64 * 64];        // [b*H+h][l][m] : sim -> attn (in place)
__device__ float g_ln[2048 * 8 * 64 * 64];       // [b][h][l][d]
__device__ float g_word[2048 * 2048];            // [b][f]

// 16 FMA from two float4s into acc[4][4]
#define TILE_FMA(acc, a, b)                                        \
    do {                                                           \
        float av_[4] = {a.x, a.y, a.z, a.w};                       \
        float bv_[4] = {b.x, b.y, b.z, b.w};                       \
        _Pragma("unroll") for (int ii_ = 0; ii_ < 4; ii_++)        \
        _Pragma("unroll") for (int jj_ = 0; jj_ < 4; jj_++)        \
            acc[ii_][jj_] += av_[ii_] * bv_[jj_];                  \
    } while (0)

// k-loop with 1-ahead register prefetch over two smem operands
#define GEMM_LOOP(acc, Abuf, Bbuf, ao, bo)                         \
    do {                                                           \
        float4 a_c = *(const float4*)&Abuf[0][ao];                 \
        float4 b_c = *(const float4*)&Bbuf[0][bo];                 \
        _Pragma("unroll") for (int k_ = 0; k_ < 64; k_++) {        \
            float4 a_ = a_c, b_ = b_c;                             \
            if (k_ < 63) {                                         \
                a_c = *(const float4*)&Abuf[k_ + 1][ao];           \
                b_c = *(const float4*)&Bbuf[k_ + 1][bo];           \
            }                                                      \
            TILE_FMA(acc, a_, b_);                                 \
        }                                                          \
    } while (0)

// ---------------- K0a: qkv table = W_emb @ W_qkv^T ----------------
__global__ __launch_bounds__(256, 5) void k_qkv(const float* __restrict__ W_emb,
                                                const float* __restrict__ W_qkv) {
    __shared__ float At[64][68];   // emb^T : At[k][v_local]
    __shared__ float Bs[64][68];   // Wqkv^T: Bs[k][r_local]
    int v0 = blockIdx.y * 64, r0 = blockIdx.x * 64;
    int t = threadIdx.x;
    for (int i = t; i < 4096; i += 256) {
        int row = i >> 6, col = i & 63;
        At[col][row] = W_emb[(size_t)(v0 + row) * 64 + col];
        Bs[col][row] = W_qkv[(size_t)(r0 + row) * 64 + col];
    }
    __syncthreads();
    int tx = t & 15, ty = t >> 4;
    float acc[4][4] = {};
    GEMM_LOOP(acc, At, Bs, 4 * ty, 4 * tx);
#pragma unroll
    for (int i = 0; i < 4; i++) {
        float4 v = make_float4(acc[i][0], acc[i][1], acc[i][2], acc[i][3]);
        *(float4*)&g_qkv[(size_t)(v0 + 4 * ty + i) * 1536 + r0 + 4 * tx] = v;
    }
}

// ---------------- K0b: fused position table ----------------
__global__ __launch_bounds__(256) void k_mtab(const float* __restrict__ W_pos) {
    int idx = blockIdx.x * 256 + threadIdx.x;     // l*4096 + mp*64 + m
    int l = idx >> 12, mp = (idx >> 6) & 63, m = idx & 63;
    float base = (float)(m - l) * (6.283185307179586f / 63.0f);
    float acc = 0.f;
    for (int i = 0; i < 31; i++) {
        float s, c;
        sincosf((float)(i + 1) * base, &s, &c);
        acc += W_pos[i * 64 + mp] * c + W_pos[(i + 31) * 64 + mp] * s;
    }
    g_M[idx] = acc * (1.0f / 62.0f);
}

// ---------------- K1: sim = Q K^T / sqrt(D), key-pad masked ----------------
__global__ __launch_bounds__(256, 5) void k_sim(const int* __restrict__ inputs) {
    __shared__ float Qt[64][68];   // Q^T: Qt[d][l]
    __shared__ float Kt[64][68];   // K^T: Kt[d][m]
    __shared__ int toks[64];
    int h = blockIdx.x, b = blockIdx.y, t = threadIdx.x;
    if (t < 64) toks[t] = inputs[b * 64 + t];
    __syncthreads();
    for (int i = t; i < 4096; i += 256) {
        int m = i >> 6, d = i & 63;
        size_t base = (size_t)toks[m] * 1536 + (size_t)h * 64 + d;
        Qt[d][m] = g_qkv[base];
        Kt[d][m] = g_qkv[base + 512];     // (NH+h)*64 = h*64 + 512
    }
    __syncthreads();
    int tx = t & 15, ty = t >> 4;
    float acc[4][4] = {};
    GEMM_LOOP(acc, Qt, Kt, 4 * ty, 4 * tx);
    int msk[4];
#pragma unroll
    for (int j = 0; j < 4; j++) msk[j] = (toks[4 * tx + j] == 0);
    size_t off = (size_t)(b * NH + h) * 4096;
#pragma unroll
    for (int i = 0; i < 4; i++) {
        float4 v;
        v.x = msk[0] ? -1e9f : acc[i][0] * 0.125f;
        v.y = msk[1] ? -1e9f : acc[i][1] * 0.125f;
        v.z = msk[2] ? -1e9f : acc[i][2] * 0.125f;
        v.w = msk[3] ? -1e9f : acc[i][3] * 0.125f;
        *(float4*)&g_S[off + (size_t)(4 * ty + i) * 64 + 4 * tx] = v;
    }
}

// ---------------- K2: pos bias (via M[l]) + softmax, in place on g_S ----------------
// acc starts at raw score (reconstructed from clipped value + pad mask), then
// accumulates bias; no separate raw-S smem buffer.
__global__ __launch_bounds__(256, 5) void k_pos_softmax(const int* __restrict__ inputs) {
    __shared__ float Ms[64][64];            // M[l]: [m'][m]
    __shared__ float Sct[64][68];           // clipped S^T: Sct[m'][r]
    __shared__ unsigned char mskS[8][64];   // pad mask for the 8 b's in this row group
    int l = blockIdx.x, r0 = blockIdx.y * 64, t = threadIdx.x;
    int b0 = r0 >> 3;
    for (int i = t; i < 1024; i += 256)
        ((float4*)&Ms[0][0])[i] = ((const float4*)(g_M + (size_t)l * 4096))[i];
    for (int i = t; i < 4096; i += 256) {
        int r = i >> 6, m = i & 63;
        float s = g_S[((size_t)(r0 + r) * 64 + l) * 64 + m];
        Sct[m][r] = (s > -1e8f) ? s : 0.f;
    }
    for (int i = t; i < 512; i += 256)
        mskS[i >> 6][i & 63] = (inputs[(b0 + (i >> 6)) * 64 + (i & 63)] == 0);
    __syncthreads();
    int tx = t & 15, ty = t >> 4;
    int bb = ty >> 1;                       // all 4 rows of this thread share one b
    float acc[4][4];
#pragma unroll
    for (int j = 0; j < 4; j++) {
        int masked = mskS[bb][4 * tx + j];
#pragma unroll
        for (int i = 0; i < 4; i++)
            acc[i][j] = masked ? -1e9f : Sct[4 * tx + j][4 * ty + i];
    }
    GEMM_LOOP(acc, Sct, Ms, 4 * ty, 4 * tx);     // acc = s + bias = z
#pragma unroll
    for (int i = 0; i < 4; i++) {
        int r = 4 * ty + i;
        float mx = fmaxf(fmaxf(acc[i][0], acc[i][1]), fmaxf(acc[i][2], acc[i][3]));
#pragma unroll
        for (int d = 1; d < 16; d <<= 1)
            mx = fmaxf(mx, __shfl_xor_sync(0xffffffffu, mx, d));
        float e[4], sm = 0.f;
#pragma unroll
        for (int j = 0; j < 4; j++) { e[j] = __expf(acc[i][j] - mx); sm += e[j]; }
#pragma unroll
        for (int d = 1; d < 16; d <<= 1)
            sm += __shfl_xor_sync(0xffffffffu, sm, d);
        float inv = 1.0f / sm;
        float4 v = make_float4(e[0] * inv, e[1] * inv, e[2] * inv, e[3] * inv);
        *(float4*)&g_S[((size_t)(r0 + r) * 64 + l) * 64 + 4 * tx] = v;
    }
}

// ---------------- K3: out = attn @ V, then layernorm over D ----------------
__global__ __launch_bounds__(256, 5) void k_av_ln(const int* __restrict__ inputs,
                                                  const float* __restrict__ ln_g,
                                                  const float* __restrict__ ln_b) {
    __shared__ float Att[64][68];  // attn^T: Att[m][l]
    __shared__ float Vs[64][64];   // V: [m][d]
    __shared__ int toks[64];
    __shared__ float gam[64], bet[64];
    int h = blockIdx.x, b = blockIdx.y, t = threadIdx.x;
    if (t < 64) { toks[t] = inputs[b * 64 + t]; gam[t] = ln_g[t]; bet[t] = ln_b[t]; }
    __syncthreads();
    size_t soff = (size_t)(b * NH + h) * 4096;
    for (int i = t; i < 4096; i += 256) {
        int row = i >> 6, col = i & 63;
        Att[col][row] = g_S[soff + i];                                  // row=l, col=m
        Vs[row][col] = g_qkv[(size_t)toks[row] * 1536 + (size_t)(2 * NH + h) * 64 + col];
    }
    __syncthreads();
    int tx = t & 15, ty = t >> 4;
    float acc[4][4] = {};
    GEMM_LOOP(acc, Att, Vs, 4 * ty, 4 * tx);
    size_t lo = (size_t)(b * NH + h) * 4096;
#pragma unroll
    for (int i = 0; i < 4; i++) {
        int l = 4 * ty + i;
        float s = acc[i][0] + acc[i][1] + acc[i][2] + acc[i][3];
        float sq = acc[i][0] * acc[i][0] + acc[i][1] * acc[i][1]
                 + acc[i][2] * acc[i][2] + acc[i][3] * acc[i][3];
#pragma unroll
        for (int d = 1; d < 16; d <<= 1) {
            s  += __shfl_xor_sync(0xffffffffu, s, d);
            sq += __shfl_xor_sync(0xffffffffu, sq, d);
        }
        float mu = s * (1.0f / 64.0f);
        float var = sq * (1.0f / 64.0f) - mu * mu;
        float inv = rsqrtf(var + 1e-5f);
        float4 v;
        v.x = (acc[i][0] - mu) * inv * gam[4 * tx + 0] + bet[4 * tx + 0];
        v.y = (acc[i][1] - mu) * inv * gam[4 * tx + 1] + bet[4 * tx + 1];
        v.z = (acc[i][2] - mu) * inv * gam[4 * tx + 2] + bet[4 * tx + 2];
        v.w = (acc[i][3] - mu) * inv * gam[4 * tx + 3] + bet[4 * tx + 3];
        *(float4*)&g_ln[lo + (size_t)l * 64 + 4 * tx] = v;
    }
}

// ---------------- K4: MLP + masked word mean, o-chunked for low regs ----------------
__global__ __launch_bounds__(256, 4) void k_mlp(const int* __restrict__ inputs,
                                                const float* __restrict__ W1,
                                                const float* __restrict__ b1,
                                                const float* __restrict__ W2,
                                                const float* __restrict__ b2) {
    __shared__ float W1s[512];        // [o][h]
    __shared__ float b1s[64];
    __shared__ float W2t[64][32];     // W2^T: W2t[o][p]
    __shared__ float b2s[32];
    __shared__ float part[4][64][37]; // [lg][d][p], pad 37 -> conflict-free
    __shared__ int toks[64];
    int b = blockIdx.x, t = threadIdx.x;
    if (t < 64) { toks[t] = inputs[b * 64 + t]; b1s[t] = b1[t]; }
    if (t < 32) b2s[t] = b2[t];
    for (int i = t; i < 512; i += 256) W1s[i] = W1[i];
    for (int i = t; i < 2048; i += 256) {
        int o = i >> 5, p = i & 31;
        W2t[o][p] = W2[p * 64 + o];
    }
    for (int i = t; i < 4 * 64 * 37; i += 256) ((float*)part)[i] = 0.f;
    __syncthreads();
    float cnt = 0.f;
    for (int m = 0; m < 64; m++) cnt += (toks[m] != 0) ? 1.f : 0.f;

    int d = t & 63, lg = t >> 6;
    float* myp = &part[lg][d][0];
#pragma unroll
    for (int oc = 0; oc < 4; oc++) {
        float hs[16];
#pragma unroll
        for (int o2 = 0; o2 < 16; o2++) hs[o2] = 0.f;
        for (int li = 0; li < 16; li++) {
            int l = lg * 16 + li;
            if (toks[l] == 0) continue;
            float ft[8];
#pragma unroll
            for (int hh = 0; hh < 8; hh++)
                ft[hh] = g_ln[(((size_t)b * 8 + hh) * 64 + l) * 64 + d];
#pragma unroll
            for (int o2 = 0; o2 < 16; o2++) {
                int o = oc * 16 + o2;
                float4 wa = *(const float4*)&W1s[o * 8];
                float4 wb = *(const float4*)&W1s[o * 8 + 4];
                float v = b1s[o]
                        + wa.x * ft[0] + wa.y * ft[1] + wa.z * ft[2] + wa.w * ft[3]
                        + wb.x * ft[4] + wb.y * ft[5] + wb.z * ft[6] + wb.w * ft[7];
                hs[o2] += fmaxf(v, 0.f);
            }
        }
#pragma unroll
        for (int o2 = 0; o2 < 16; o2++) {
            int o = oc * 16 + o2;
            float hv = hs[o2];
#pragma unroll
            for (int p = 0; p < 32; p++) myp[p] += W2t[o][p] * hv;
        }
    }
    __syncthreads();
    float invc = 1.0f / cnt;
    for (int f = t; f < 2048; f += 256) {
        int dd = f >> 5, p = f & 31;
        float w = part[0][dd][p] + part[1][dd][p] + part[2][dd][p] + part[3][dd][p];
        g_word[(size_t)b * 2048 + f] = w * invc + b2s[p];
    }
}

// ---------------- K5: name mean over n_words ----------------
__global__ __launch_bounds__(256) void k_name(float* __restrict__ out, int n_words, int total) {
    int idx = blockIdx.x * 256 + threadIdx.x;
    if (idx >= total) return;
    int g = idx >> 11, f = idx & 2047;
    float s = 0.f;
    for (int w = 0; w < n_words; w++)
        s += g_word[(size_t)(g * n_words + w) * 2048 + f];
    out[idx] = s / (float)n_words;
}

// ---------------- launch ----------------
extern "C" void kernel_launch(void* const* d_in, const int* in_sizes, int n_in,
                              void* d_out, int out_size) {
    const int* inputs  = (const int*)d_in[0];
    const float* W_emb = (const float*)d_in[1];
    const float* W_qkv = (const float*)d_in[2];
    const float* W_pos = (const float*)d_in[3];
    const float* ln_g  = (const float*)d_in[4];
    const float* ln_b  = (const float*)d_in[5];
    const float* W1    = (const float*)d_in[6];
    const float* b1    = (const float*)d_in[7];
    const float* W2    = (const float*)d_in[8];
    const float* b2    = (const float*)d_in[9];

    int B = in_sizes[0] / 64;                         // 2048
    int V = in_sizes[1] / 64;                         // 4096
    int n_words = (int)(((long long)B * 2048) / out_size);

    k_qkv<<<dim3(24, V / 64), 256>>>(W_emb, W_qkv);
    k_mtab<<<1024, 256>>>(W_pos);
    k_sim<<<dim3(NH, B), 256>>>(inputs);
    k_pos_softmax<<<dim3(64, (B * NH) / 64), 256>>>(inputs);
    k_av_ln<<<dim3(NH, B), 256>>>(inputs, ln_g, ln_b);
    k_mlp<<<B, 256>>>(inputs, W1, b1, W2, b2);
    k_name<<<(out_size + 255) / 256, 256>>>((float*)d_out, n_words, out_size);
}

// round 5
// speedup vs baseline: 3.4908x; 1.4169x over previous
#include <cuda_runtime.h>
#include <math.h>

#define NH 8

// ---------------- scratch (static __device__, no allocation) ----------------
__device__ float g_qkv[4096 * 24 * 64];          // [v][jh][d], jh: 0-7 q, 8-15 k, 16-23 v
__device__ float g_M[64 * 64 * 64];              // [l][m'][m]
__device__ float g_S[2048 * 8 * 64 * 64];        // [b*H+h][l][m] : sim -> attn (in place)
__device__ float g_ln[2048 * 8 * 64 * 64];       // [b][h][l][d]
__device__ float g_word[2048 * 2048];            // [b][f]

typedef unsigned long long u64;

__device__ __forceinline__ void fma2(u64& d, u64 a, u64 b) {
    asm("fma.rn.f32x2 %0, %1, %2, %3;" : "=l"(d) : "l"(a), "l"(b), "l"(d));
}
__device__ __forceinline__ u64 pk2(float lo, float hi) {
    u64 r; asm("mov.b64 %0, {%1, %2};" : "=l"(r) : "f"(lo), "f"(hi)); return r;
}
__device__ __forceinline__ float2 up2(u64 v) {
    float2 r; asm("mov.b64 {%0, %1}, %2;" : "=f"(r.x), "=f"(r.y) : "l"(v)); return r;
}

// 4x4 tile via f32x2: A dup-stored [k][2r], B plain k-major [k][m].
// acc2[i][0] = (out[i][4tx+0], out[i][4tx+1]), acc2[i][1] = (out[i][4tx+2], out[i][4tx+3])
#define GEMM2(acc2, Ad, Bsm, ty, tx)                                   \
    _Pragma("unroll") for (int k_ = 0; k_ < 64; k_++) {                \
        u64 a0 = *(const u64*)&Ad[k_][2 * (4 * (ty) + 0)];             \
        u64 a1 = *(const u64*)&Ad[k_][2 * (4 * (ty) + 1)];             \
        u64 a2 = *(const u64*)&Ad[k_][2 * (4 * (ty) + 2)];             \
        u64 a3 = *(const u64*)&Ad[k_][2 * (4 * (ty) + 3)];             \
        ulonglong2 b_ = *(const ulonglong2*)&Bsm[k_][4 * (tx)];        \
        fma2(acc2[0][0], a0, b_.x); fma2(acc2[0][1], a0, b_.y);        \
        fma2(acc2[1][0], a1, b_.x); fma2(acc2[1][1], a1, b_.y);        \
        fma2(acc2[2][0], a2, b_.x); fma2(acc2[2][1], a2, b_.y);        \
        fma2(acc2[3][0], a3, b_.x); fma2(acc2[3][1], a3, b_.y);        \
    }

#define UNPACK_ACC(acc, acc2)                                          \
    _Pragma("unroll") for (int i_ = 0; i_ < 4; i_++) {                 \
        float2 p0_ = up2(acc2[i_][0]), p1_ = up2(acc2[i_][1]);         \
        acc[i_][0] = p0_.x; acc[i_][1] = p0_.y;                        \
        acc[i_][2] = p1_.x; acc[i_][3] = p1_.y;                        \
    }

// ---------------- K0a: qkv table = W_emb @ W_qkv^T ----------------
__global__ __launch_bounds__(256) void k_qkv(const float* __restrict__ W_emb,
                                             const float* __restrict__ W_qkv) {
    __shared__ float Ad[64][128];   // W_emb^T dup: Ad[k][2v] = W_emb[v0+v][k]
    __shared__ float Bs[64][64];    // Wqkv^T:      Bs[k][r]  = W_qkv[r0+r][k]
    int v0 = blockIdx.y * 64, r0 = blockIdx.x * 64;
    int t = threadIdx.x;
    for (int i = t; i < 1024; i += 256) {
        int v = i & 63, k0 = (i >> 6) * 4;
        float4 e = *(const float4*)&W_emb[(size_t)(v0 + v) * 64 + k0];
        Ad[k0 + 0][2 * v] = e.x; Ad[k0 + 0][2 * v + 1] = e.x;
        Ad[k0 + 1][2 * v] = e.y; Ad[k0 + 1][2 * v + 1] = e.y;
        Ad[k0 + 2][2 * v] = e.z; Ad[k0 + 2][2 * v + 1] = e.z;
        Ad[k0 + 3][2 * v] = e.w; Ad[k0 + 3][2 * v + 1] = e.w;
    }
    for (int i = t; i < 1024; i += 256) {
        int r = i & 63, k0 = (i >> 6) * 4;
        float4 w = *(const float4*)&W_qkv[(size_t)(r0 + r) * 64 + k0];
        Bs[k0 + 0][r] = w.x; Bs[k0 + 1][r] = w.y;
        Bs[k0 + 2][r] = w.z; Bs[k0 + 3][r] = w.w;
    }
    __syncthreads();
    int tx = t & 15, ty = t >> 4;
    u64 acc2[4][2] = {};
    GEMM2(acc2, Ad, Bs, ty, tx);
    float acc[4][4];
    UNPACK_ACC(acc, acc2);
#pragma unroll
    for (int i = 0; i < 4; i++) {
        float4 v = make_float4(acc[i][0], acc[i][1], acc[i][2], acc[i][3]);
        *(float4*)&g_qkv[(size_t)(v0 + 4 * ty + i) * 1536 + r0 + 4 * tx] = v;
    }
}

// ---------------- K0b: fused position table ----------------
__global__ __launch_bounds__(256) void k_mtab(const float* __restrict__ W_pos) {
    int idx = blockIdx.x * 256 + threadIdx.x;     // l*4096 + mp*64 + m
    int l = idx >> 12, mp = (idx >> 6) & 63, m = idx & 63;
    float base = (float)(m - l) * (6.283185307179586f / 63.0f);
    float acc = 0.f;
    for (int i = 0; i < 31; i++) {
        float s, c;
        sincosf((float)(i + 1) * base, &s, &c);
        acc += W_pos[i * 64 + mp] * c + W_pos[(i + 31) * 64 + mp] * s;
    }
    g_M[idx] = acc * (1.0f / 62.0f);
}

// ---------------- K1: sim = Q K^T / sqrt(D), key-pad masked ----------------
__global__ __launch_bounds__(256) void k_sim(const int* __restrict__ inputs) {
    __shared__ float Ad[64][128];   // Q^T dup: Ad[d][2l] = Q[l][d]
    __shared__ float Bs[64][64];    // K^T:     Bs[d][m]  = K[m][d]
    int h = blockIdx.x, b = blockIdx.y, t = threadIdx.x;
    for (int i = t; i < 1024; i += 256) {
        int l = i & 63, d0 = (i >> 6) * 4;
        int tok = inputs[b * 64 + l];
        float4 q = *(const float4*)&g_qkv[(size_t)tok * 1536 + h * 64 + d0];
        Ad[d0 + 0][2 * l] = q.x; Ad[d0 + 0][2 * l + 1] = q.x;
        Ad[d0 + 1][2 * l] = q.y; Ad[d0 + 1][2 * l + 1] = q.y;
        Ad[d0 + 2][2 * l] = q.z; Ad[d0 + 2][2 * l + 1] = q.z;
        Ad[d0 + 3][2 * l] = q.w; Ad[d0 + 3][2 * l + 1] = q.w;
    }
    for (int i = t; i < 1024; i += 256) {
        int m = i & 63, d0 = (i >> 6) * 4;
        int tok = inputs[b * 64 + m];
        float4 kv = *(const float4*)&g_qkv[(size_t)tok * 1536 + (NH + h) * 64 + d0];
        Bs[d0 + 0][m] = kv.x; Bs[d0 + 1][m] = kv.y;
        Bs[d0 + 2][m] = kv.z; Bs[d0 + 3][m] = kv.w;
    }
    __syncthreads();
    int tx = t & 15, ty = t >> 4;
    u64 acc2[4][2] = {};
    GEMM2(acc2, Ad, Bs, ty, tx);
    float acc[4][4];
    UNPACK_ACC(acc, acc2);
    int msk[4];
#pragma unroll
    for (int j = 0; j < 4; j++) msk[j] = (inputs[b * 64 + 4 * tx + j] == 0);
    size_t off = (size_t)(b * NH + h) * 4096;
#pragma unroll
    for (int i = 0; i < 4; i++) {
        float4 v;
        v.x = msk[0] ? -1e9f : acc[i][0] * 0.125f;
        v.y = msk[1] ? -1e9f : acc[i][1] * 0.125f;
        v.z = msk[2] ? -1e9f : acc[i][2] * 0.125f;
        v.w = msk[3] ? -1e9f : acc[i][3] * 0.125f;
        *(float4*)&g_S[off + (size_t)(4 * ty + i) * 64 + 4 * tx] = v;
    }
}

// ---------------- K2: pos bias (via M[l]) + softmax, in place on g_S ----------------
// acc init = raw S (already -1e9 at masked cols); A operand = clipped S dup-transposed.
__global__ __launch_bounds__(256) void k_pos_softmax() {
    __shared__ float Ad[64][128];   // clipped S^T dup: Ad[mp][2r]
    __shared__ float Ms[64][64];    // M[l]: [mp][m]
    int l = blockIdx.x, r0 = blockIdx.y * 64, t = threadIdx.x;
    for (int i = t; i < 1024; i += 256)
        ((float4*)Ms)[i] = ((const float4*)(g_M + (size_t)l * 4096))[i];
    for (int i = t; i < 1024; i += 256) {
        int r = i & 63, m0 = (i >> 6) * 4;
        float4 s = *(const float4*)&g_S[((size_t)(r0 + r) * 64 + l) * 64 + m0];
        float c0 = (s.x > -1e8f) ? s.x : 0.f;
        float c1 = (s.y > -1e8f) ? s.y : 0.f;
        float c2 = (s.z > -1e8f) ? s.z : 0.f;
        float c3 = (s.w > -1e8f) ? s.w : 0.f;
        Ad[m0 + 0][2 * r] = c0; Ad[m0 + 0][2 * r + 1] = c0;
        Ad[m0 + 1][2 * r] = c1; Ad[m0 + 1][2 * r + 1] = c1;
        Ad[m0 + 2][2 * r] = c2; Ad[m0 + 2][2 * r + 1] = c2;
        Ad[m0 + 3][2 * r] = c3; Ad[m0 + 3][2 * r + 1] = c3;
    }
    __syncthreads();
    int tx = t & 15, ty = t >> 4;
    // init acc with raw scores straight from gmem (L1/L2 hot from fill)
    u64 acc2[4][2];
#pragma unroll
    for (int i = 0; i < 4; i++) {
        float4 s = *(const float4*)&g_S[((size_t)(r0 + 4 * ty + i) * 64 + l) * 64 + 4 * tx];
        acc2[i][0] = pk2(s.x, s.y);
        acc2[i][1] = pk2(s.z, s.w);
    }
    GEMM2(acc2, Ad, Ms, ty, tx);     // acc = s + bias = z
    float acc[4][4];
    UNPACK_ACC(acc, acc2);
#pragma unroll
    for (int i = 0; i < 4; i++) {
        int r = 4 * ty + i;
        float mx = fmaxf(fmaxf(acc[i][0], acc[i][1]), fmaxf(acc[i][2], acc[i][3]));
#pragma unroll
        for (int d = 1; d < 16; d <<= 1)
            mx = fmaxf(mx, __shfl_xor_sync(0xffffffffu, mx, d));
        float e[4], sm = 0.f;
#pragma unroll
        for (int j = 0; j < 4; j++) { e[j] = __expf(acc[i][j] - mx); sm += e[j]; }
#pragma unroll
        for (int d = 1; d < 16; d <<= 1)
            sm += __shfl_xor_sync(0xffffffffu, sm, d);
        float inv = 1.0f / sm;
        float4 v = make_float4(e[0] * inv, e[1] * inv, e[2] * inv, e[3] * inv);
        *(float4*)&g_S[((size_t)(r0 + r) * 64 + l) * 64 + 4 * tx] = v;
    }
}

// ---------------- K3: out = attn @ V, then layernorm over D ----------------
__global__ __launch_bounds__(256) void k_av_ln(const int* __restrict__ inputs,
                                               const float* __restrict__ ln_g,
                                               const float* __restrict__ ln_b) {
    __shared__ float Ad[64][128];   // attn^T dup: Ad[m][2l]
    __shared__ float Vs[64][64];    // V: [m][d]
    int h = blockIdx.x, b = blockIdx.y, t = threadIdx.x;
    size_t soff = (size_t)(b * NH + h) * 4096;
    for (int i = t; i < 1024; i += 256) {
        int l = i & 63, m0 = (i >> 6) * 4;
        float4 a = *(const float4*)&g_S[soff + (size_t)l * 64 + m0];
        Ad[m0 + 0][2 * l] = a.x; Ad[m0 + 0][2 * l + 1] = a.x;
        Ad[m0 + 1][2 * l] = a.y; Ad[m0 + 1][2 * l + 1] = a.y;
        Ad[m0 + 2][2 * l] = a.z; Ad[m0 + 2][2 * l + 1] = a.z;
        Ad[m0 + 3][2 * l] = a.w; Ad[m0 + 3][2 * l + 1] = a.w;
    }
    for (int i = t; i < 1024; i += 256) {
        int m = i >> 4, d0 = (i & 15) * 4;
        int tok = inputs[b * 64 + m];
        float4 v = *(const float4*)&g_qkv[(size_t)tok * 1536 + (2 * NH + h) * 64 + d0];
        *(float4*)&Vs[m][d0] = v;
    }
    __syncthreads();
    int tx = t & 15, ty = t >> 4;
    u64 acc2[4][2] = {};
    GEMM2(acc2, Ad, Vs, ty, tx);
    float acc[4][4];
    UNPACK_ACC(acc, acc2);
    float g0 = ln_g[4 * tx + 0], g1 = ln_g[4 * tx + 1], g2 = ln_g[4 * tx + 2], g3 = ln_g[4 * tx + 3];
    float t0 = ln_b[4 * tx + 0], t1 = ln_b[4 * tx + 1], t2 = ln_b[4 * tx + 2], t3 = ln_b[4 * tx + 3];
    size_t lo = (size_t)(b * NH + h) * 4096;
#pragma unroll
    for (int i = 0; i < 4; i++) {
        int l = 4 * ty + i;
        float s = acc[i][0] + acc[i][1] + acc[i][2] + acc[i][3];
        float sq = acc[i][0] * acc[i][0] + acc[i][1] * acc[i][1]
                 + acc[i][2] * acc[i][2] + acc[i][3] * acc[i][3];
#pragma unroll
        for (int d = 1; d < 16; d <<= 1) {
            s  += __shfl_xor_sync(0xffffffffu, s, d);
            sq += __shfl_xor_sync(0xffffffffu, sq, d);
        }
        float mu = s * (1.0f / 64.0f);
        float var = sq * (1.0f / 64.0f) - mu * mu;
        float inv = rsqrtf(var + 1e-5f);
        float4 v;
        v.x = (acc[i][0] - mu) * inv * g0 + t0;
        v.y = (acc[i][1] - mu) * inv * g1 + t1;
        v.z = (acc[i][2] - mu) * inv * g2 + t2;
        v.w = (acc[i][3] - mu) * inv * g3 + t3;
        *(float4*)&g_ln[lo + (size_t)l * 64 + 4 * tx] = v;
    }
}

// ---------------- K4: MLP + masked word mean, register accumulators ----------------
__global__ __launch_bounds__(256, 3) void k_mlp(const int* __restrict__ inputs,
                                                const float* __restrict__ W1,
                                                const float* __restrict__ b1,
                                                const float* __restrict__ W2,
                                                const float* __restrict__ b2) {
    __shared__ float W1s[512];        // [o][h]
    __shared__ float b1s[64];
    __shared__ float W2t[64][32];     // W2^T: W2t[o][p]
    __shared__ float b2s[32];
    __shared__ float part[4][64][33]; // [lg][d][p]
    __shared__ int toks[64];
    int b = blockIdx.x, t = threadIdx.x;
    if (t < 64) { toks[t] = inputs[b * 64 + t]; b1s[t] = b1[t]; }
    if (t < 32) b2s[t] = b2[t];
    for (int i = t; i < 512; i += 256) W1s[i] = W1[i];
    for (int i = t; i < 2048; i += 256) {
        int o = i >> 5, p = i & 31;
        W2t[o][p] = W2[p * 64 + o];
    }
    __syncthreads();
    float cnt = 0.f;
    for (int m = 0; m < 64; m++) cnt += (toks[m] != 0) ? 1.f : 0.f;

    int d = t & 63, lg = t >> 6;
    float acc[32];
#pragma unroll
    for (int p = 0; p < 32; p++) acc[p] = 0.f;
#pragma unroll 1
    for (int oc = 0; oc < 4; oc++) {
        float hs[16];
#pragma unroll
        for (int o2 = 0; o2 < 16; o2++) hs[o2] = 0.f;
        for (int li = 0; li < 16; li++) {
            int l = lg * 16 + li;
            if (toks[l] == 0) continue;
            float ft[8];
#pragma unroll
            for (int hh = 0; hh < 8; hh++)
                ft[hh] = g_ln[(((size_t)b * 8 + hh) * 64 + l) * 64 + d];
#pragma unroll
            for (int o2 = 0; o2 < 16; o2++) {
                int o = oc * 16 + o2;
                float4 wa = *(const float4*)&W1s[o * 8];
                float4 wb = *(const float4*)&W1s[o * 8 + 4];
                float v = b1s[o]
                        + wa.x * ft[0] + wa.y * ft[1] + wa.z * ft[2] + wa.w * ft[3]
                        + wb.x * ft[4] + wb.y * ft[5] + wb.z * ft[6] + wb.w * ft[7];
                hs[o2] += fmaxf(v, 0.f);
            }
        }
#pragma unroll
        for (int o2 = 0; o2 < 16; o2++) {
            int o = oc * 16 + o2;
            float hv = hs[o2];
#pragma unroll
            for (int q = 0; q < 8; q++) {
                float4 w = *(const float4*)&W2t[o][4 * q];
                acc[4 * q + 0] += w.x * hv;
                acc[4 * q + 1] += w.y * hv;
                acc[4 * q + 2] += w.z * hv;
                acc[4 * q + 3] += w.w * hv;
            }
        }
    }
#pragma unroll
    for (int p = 0; p < 32; p++) part[lg][d][p] = acc[p];
    __syncthreads();
    float invc = 1.0f / cnt;
    for (int f = t; f < 2048; f += 256) {
        int dd = f >> 5, p = f & 31;
        float w = part[0][dd][p] + part[1][dd][p] + part[2][dd][p] + part[3][dd][p];
        g_word[(size_t)b * 2048 + f] = w * invc + b2s[p];
    }
}

// ---------------- K5: name mean over n_words ----------------
__global__ __launch_bounds__(256) void k_name(float* __restrict__ out, int n_words, int total) {
    int idx = blockIdx.x * 256 + threadIdx.x;
    if (idx >= total) return;
    int g = idx >> 11, f = idx & 2047;
    float s = 0.f;
    for (int w = 0; w < n_words; w++)
        s += g_word[(size_t)(g * n_words + w) * 2048 + f];
    out[idx] = s / (float)n_words;
}

// ---------------- launch ----------------
extern "C" void kernel_launch(void* const* d_in, const int* in_sizes, int n_in,
                              void* d_out, int out_size) {
    const int* inputs  = (const int*)d_in[0];
    const float* W_emb = (const float*)d_in[1];
    const float* W_qkv = (const float*)d_in[2];
    const float* W_pos = (const float*)d_in[3];
    const float* ln_g  = (const float*)d_in[4];
    const float* ln_b  = (const float*)d_in[5];
    const float* W1    = (const float*)d_in[6];
    const float* b1    = (const float*)d_in[7];
    const float* W2    = (const float*)d_in[8];
    const float* b2    = (const float*)d_in[9];

    int B = in_sizes[0] / 64;                         // 2048
    int V = in_sizes[1] / 64;                         // 4096
    int n_words = (int)(((long long)B * 2048) / out_size);

    k_qkv<<<dim3(24, V / 64), 256>>>(W_emb, W_qkv);
    k_mtab<<<1024, 256>>>(W_pos);
    k_sim<<<dim3(NH, B), 256>>>(inputs);
    k_pos_softmax<<<dim3(64, (B * NH) / 64), 256>>>();
    k_av_ln<<<dim3(NH, B), 256>>>(inputs, ln_g, ln_b);
    k_mlp<<<B, 256>>>(inputs, W1, b1, W2, b2);
    k_name<<<(out_size + 255) / 256, 256>>>((float*)d_out, n_words, out_size);
}

// round 6
// speedup vs baseline: 4.1923x; 1.2010x over previous
#include <cuda_runtime.h>
#include <math.h>

#define NH 8

// ---------------- scratch (static __device__, no allocation) ----------------
__device__ float g_qkv[4096 * 24 * 64];          // [v][jh][d], jh: 0-7 q, 8-15 k, 16-23 v
__device__ float g_M[64 * 64 * 64];              // [l][m'][m]
__device__ float g_S[2048 * 8 * 64 * 64];        // [b*H+h][l][m] : sim -> attn (in place)
__device__ float g_ln[2048 * 8 * 64 * 64];       // [b][h][l][d]
__device__ float g_word[2048 * 2048];            // [b][f]

typedef unsigned long long u64;

__device__ __forceinline__ void fma2(u64& d, u64 a, u64 b) {
    asm("fma.rn.f32x2 %0, %1, %2, %3;" : "=l"(d) : "l"(a), "l"(b), "l"(d));
}
__device__ __forceinline__ u64 pk2(float lo, float hi) {
    u64 r; asm("mov.b64 %0, {%1, %2};" : "=l"(r) : "f"(lo), "f"(hi)); return r;
}
__device__ __forceinline__ float2 up2(u64 v) {
    float2 r; asm("mov.b64 {%0, %1}, %2;" : "=f"(r.x), "=f"(r.y) : "l"(v)); return r;
}

// 8 rows x 4 cols per thread. A k-major [k][r] (row pairs natural u64),
// B k-major [k][m] (dup pairs via ALU mov). 3 LDS + 4 MOV + 16 FFMA2 per k.
// acc2[p][c] = packed (out[8ty+2p][4tx+c], out[8ty+2p+1][4tx+c])
#define GEMM8x4(acc2, Asm, Bsm, ty, tx)                                \
    _Pragma("unroll") for (int k_ = 0; k_ < 64; k_++) {                \
        ulonglong2 aA = *(const ulonglong2*)&Asm[k_][8 * (ty)];        \
        ulonglong2 aB = *(const ulonglong2*)&Asm[k_][8 * (ty) + 4];    \
        float4 bv = *(const float4*)&Bsm[k_][4 * (tx)];                \
        u64 b0 = pk2(bv.x, bv.x), b1 = pk2(bv.y, bv.y);                \
        u64 b2 = pk2(bv.z, bv.z), b3 = pk2(bv.w, bv.w);                \
        fma2(acc2[0][0], aA.x, b0); fma2(acc2[0][1], aA.x, b1);        \
        fma2(acc2[0][2], aA.x, b2); fma2(acc2[0][3], aA.x, b3);        \
        fma2(acc2[1][0], aA.y, b0); fma2(acc2[1][1], aA.y, b1);        \
        fma2(acc2[1][2], aA.y, b2); fma2(acc2[1][3], aA.y, b3);        \
        fma2(acc2[2][0], aB.x, b0); fma2(acc2[2][1], aB.x, b1);        \
        fma2(acc2[2][2], aB.x, b2); fma2(acc2[2][3], aB.x, b3);        \
        fma2(acc2[3][0], aB.y, b0); fma2(acc2[3][1], aB.y, b1);        \
        fma2(acc2[3][2], aB.y, b2); fma2(acc2[3][3], aB.y, b3);        \
    }

// ---------------- K0a: qkv table = W_emb @ W_qkv^T ----------------
__global__ __launch_bounds__(128) void k_qkv(const float* __restrict__ W_emb,
                                             const float* __restrict__ W_qkv) {
    __shared__ float As[64][64];   // emb^T : As[k][v]
    __shared__ float Bs[64][64];   // Wqkv^T: Bs[k][r]
    int v0 = blockIdx.y * 64, r0 = blockIdx.x * 64;
    int t = threadIdx.x;
    for (int i = t; i < 1024; i += 128) {
        int row = i & 63, k0 = (i >> 6) * 4;
        float4 e = *(const float4*)&W_emb[(size_t)(v0 + row) * 64 + k0];
        As[k0 + 0][row] = e.x; As[k0 + 1][row] = e.y;
        As[k0 + 2][row] = e.z; As[k0 + 3][row] = e.w;
        float4 w = *(const float4*)&W_qkv[(size_t)(r0 + row) * 64 + k0];
        Bs[k0 + 0][row] = w.x; Bs[k0 + 1][row] = w.y;
        Bs[k0 + 2][row] = w.z; Bs[k0 + 3][row] = w.w;
    }
    __syncthreads();
    int tx = t & 15, ty = t >> 4;
    u64 acc2[4][4] = {};
    GEMM8x4(acc2, As, Bs, ty, tx);
#pragma unroll
    for (int p = 0; p < 4; p++) {
        float2 c0 = up2(acc2[p][0]), c1 = up2(acc2[p][1]);
        float2 c2 = up2(acc2[p][2]), c3 = up2(acc2[p][3]);
        int re = 8 * ty + 2 * p;
        *(float4*)&g_qkv[(size_t)(v0 + re) * 1536 + r0 + 4 * tx] =
            make_float4(c0.x, c1.x, c2.x, c3.x);
        *(float4*)&g_qkv[(size_t)(v0 + re + 1) * 1536 + r0 + 4 * tx] =
            make_float4(c0.y, c1.y, c2.y, c3.y);
    }
}

// ---------------- K0b: fused position table ----------------
__global__ __launch_bounds__(256) void k_mtab(const float* __restrict__ W_pos) {
    int idx = blockIdx.x * 256 + threadIdx.x;     // l*4096 + mp*64 + m
    int l = idx >> 12, mp = (idx >> 6) & 63, m = idx & 63;
    float base = (float)(m - l) * (6.283185307179586f / 63.0f);
    float acc = 0.f;
    for (int i = 0; i < 31; i++) {
        float s, c;
        sincosf((float)(i + 1) * base, &s, &c);
        acc += W_pos[i * 64 + mp] * c + W_pos[(i + 31) * 64 + mp] * s;
    }
    g_M[idx] = acc * (1.0f / 62.0f);
}

// ---------------- K1: sim = Q K^T / sqrt(D), key-pad masked ----------------
__global__ __launch_bounds__(128) void k_sim(const int* __restrict__ inputs) {
    __shared__ float Qt[64][64];   // Q^T: Qt[d][l]
    __shared__ float Kt[64][64];   // K^T: Kt[d][m]
    int h = blockIdx.x, b = blockIdx.y, t = threadIdx.x;
    for (int i = t; i < 1024; i += 128) {
        int m = i & 63, d0 = (i >> 6) * 4;
        int tok = inputs[b * 64 + m];
        size_t base = (size_t)tok * 1536 + h * 64 + d0;
        float4 q = *(const float4*)&g_qkv[base];
        Qt[d0 + 0][m] = q.x; Qt[d0 + 1][m] = q.y;
        Qt[d0 + 2][m] = q.z; Qt[d0 + 3][m] = q.w;
        float4 kv = *(const float4*)&g_qkv[base + 512];
        Kt[d0 + 0][m] = kv.x; Kt[d0 + 1][m] = kv.y;
        Kt[d0 + 2][m] = kv.z; Kt[d0 + 3][m] = kv.w;
    }
    __syncthreads();
    int tx = t & 15, ty = t >> 4;
    u64 acc2[4][4] = {};
    GEMM8x4(acc2, Qt, Kt, ty, tx);
    int msk[4];
#pragma unroll
    for (int j = 0; j < 4; j++) msk[j] = (inputs[b * 64 + 4 * tx + j] == 0);
    size_t off = (size_t)(b * NH + h) * 4096;
#pragma unroll
    for (int p = 0; p < 4; p++) {
        float2 c0 = up2(acc2[p][0]), c1 = up2(acc2[p][1]);
        float2 c2 = up2(acc2[p][2]), c3 = up2(acc2[p][3]);
        int re = 8 * ty + 2 * p;
        float4 ve, vo;
        ve.x = msk[0] ? -1e9f : c0.x * 0.125f;  vo.x = msk[0] ? -1e9f : c0.y * 0.125f;
        ve.y = msk[1] ? -1e9f : c1.x * 0.125f;  vo.y = msk[1] ? -1e9f : c1.y * 0.125f;
        ve.z = msk[2] ? -1e9f : c2.x * 0.125f;  vo.z = msk[2] ? -1e9f : c2.y * 0.125f;
        ve.w = msk[3] ? -1e9f : c3.x * 0.125f;  vo.w = msk[3] ? -1e9f : c3.y * 0.125f;
        *(float4*)&g_S[off + (size_t)re * 64 + 4 * tx] = ve;
        *(float4*)&g_S[off + (size_t)(re + 1) * 64 + 4 * tx] = vo;
    }
}

// ---------------- K2: pos bias (via M[l]) + softmax, in place on g_S ----------------
__global__ __launch_bounds__(128) void k_pos_softmax() {
    __shared__ float Sct[64][64];  // clipped S^T: Sct[mp][r]
    __shared__ float Ms[64][64];   // M[l]: [mp][m]
    int l = blockIdx.x, r0 = blockIdx.y * 64, t = threadIdx.x;
    for (int i = t; i < 1024; i += 128)
        ((float4*)Ms)[i] = ((const float4*)(g_M + (size_t)l * 4096))[i];
    for (int i = t; i < 1024; i += 128) {
        int r = i & 63, m0 = (i >> 6) * 4;
        float4 s = *(const float4*)&g_S[((size_t)(r0 + r) * 64 + l) * 64 + m0];
        Sct[m0 + 0][r] = (s.x > -1e8f) ? s.x : 0.f;
        Sct[m0 + 1][r] = (s.y > -1e8f) ? s.y : 0.f;
        Sct[m0 + 2][r] = (s.z > -1e8f) ? s.z : 0.f;
        Sct[m0 + 3][r] = (s.w > -1e8f) ? s.w : 0.f;
    }
    __syncthreads();
    int tx = t & 15, ty = t >> 4;
    // init acc with raw scores from gmem (rows just touched -> L1/L2 hot)
    u64 acc2[4][4];
#pragma unroll
    for (int p = 0; p < 4; p++) {
        int re = 8 * ty + 2 * p;
        float4 se = *(const float4*)&g_S[((size_t)(r0 + re) * 64 + l) * 64 + 4 * tx];
        float4 so = *(const float4*)&g_S[((size_t)(r0 + re + 1) * 64 + l) * 64 + 4 * tx];
        acc2[p][0] = pk2(se.x, so.x);
        acc2[p][1] = pk2(se.y, so.y);
        acc2[p][2] = pk2(se.z, so.z);
        acc2[p][3] = pk2(se.w, so.w);
    }
    GEMM8x4(acc2, Sct, Ms, ty, tx);     // acc = s + bias = z
#pragma unroll
    for (int p = 0; p < 4; p++) {
        float2 c0 = up2(acc2[p][0]), c1 = up2(acc2[p][1]);
        float2 c2 = up2(acc2[p][2]), c3 = up2(acc2[p][3]);
        float ze[4] = {c0.x, c1.x, c2.x, c3.x};
        float zo[4] = {c0.y, c1.y, c2.y, c3.y};
        int re = 8 * ty + 2 * p;
#pragma unroll
        for (int s = 0; s < 2; s++) {
            float* z = s ? zo : ze;
            float mx = fmaxf(fmaxf(z[0], z[1]), fmaxf(z[2], z[3]));
#pragma unroll
            for (int d = 1; d < 16; d <<= 1)
                mx = fmaxf(mx, __shfl_xor_sync(0xffffffffu, mx, d));
            float e[4], sm = 0.f;
#pragma unroll
            for (int j = 0; j < 4; j++) { e[j] = __expf(z[j] - mx); sm += e[j]; }
#pragma unroll
            for (int d = 1; d < 16; d <<= 1)
                sm += __shfl_xor_sync(0xffffffffu, sm, d);
            float inv = 1.0f / sm;
            float4 v = make_float4(e[0] * inv, e[1] * inv, e[2] * inv, e[3] * inv);
            *(float4*)&g_S[((size_t)(r0 + re + s) * 64 + l) * 64 + 4 * tx] = v;
        }
    }
}

// ---------------- K3: out = attn @ V, then layernorm over D ----------------
__global__ __launch_bounds__(128) void k_av_ln(const int* __restrict__ inputs,
                                               const float* __restrict__ ln_g,
                                               const float* __restrict__ ln_b) {
    __shared__ float Att[64][64];  // attn^T: Att[m][l]
    __shared__ float Vs[64][64];   // V: [m][d]
    int h = blockIdx.x, b = blockIdx.y, t = threadIdx.x;
    size_t soff = (size_t)(b * NH + h) * 4096;
    for (int i = t; i < 1024; i += 128) {
        int l = i & 63, m0 = (i >> 6) * 4;
        float4 a = *(const float4*)&g_S[soff + (size_t)l * 64 + m0];
        Att[m0 + 0][l] = a.x; Att[m0 + 1][l] = a.y;
        Att[m0 + 2][l] = a.z; Att[m0 + 3][l] = a.w;
    }
    for (int i = t; i < 1024; i += 128) {
        int m = i >> 4, d0 = (i & 15) * 4;
        int tok = inputs[b * 64 + m];
        *(float4*)&Vs[m][d0] =
            *(const float4*)&g_qkv[(size_t)tok * 1536 + (2 * NH + h) * 64 + d0];
    }
    __syncthreads();
    int tx = t & 15, ty = t >> 4;
    u64 acc2[4][4] = {};
    GEMM8x4(acc2, Att, Vs, ty, tx);
    float g0 = ln_g[4 * tx + 0], g1 = ln_g[4 * tx + 1], g2 = ln_g[4 * tx + 2], g3 = ln_g[4 * tx + 3];
    float t0 = ln_b[4 * tx + 0], t1 = ln_b[4 * tx + 1], t2 = ln_b[4 * tx + 2], t3 = ln_b[4 * tx + 3];
    size_t lo = (size_t)(b * NH + h) * 4096;
#pragma unroll
    for (int p = 0; p < 4; p++) {
        float2 c0 = up2(acc2[p][0]), c1 = up2(acc2[p][1]);
        float2 c2 = up2(acc2[p][2]), c3 = up2(acc2[p][3]);
        float ae[4] = {c0.x, c1.x, c2.x, c3.x};
        float ao[4] = {c0.y, c1.y, c2.y, c3.y};
        int re = 8 * ty + 2 * p;
#pragma unroll
        for (int s = 0; s < 2; s++) {
            float* a = s ? ao : ae;
            float sm = a[0] + a[1] + a[2] + a[3];
            float sq = a[0] * a[0] + a[1] * a[1] + a[2] * a[2] + a[3] * a[3];
#pragma unroll
            for (int d = 1; d < 16; d <<= 1) {
                sm += __shfl_xor_sync(0xffffffffu, sm, d);
                sq += __shfl_xor_sync(0xffffffffu, sq, d);
            }
            float mu = sm * (1.0f / 64.0f);
            float var = sq * (1.0f / 64.0f) - mu * mu;
            float inv = rsqrtf(var + 1e-5f);
            float4 v;
            v.x = (a[0] - mu) * inv * g0 + t0;
            v.y = (a[1] - mu) * inv * g1 + t1;
            v.z = (a[2] - mu) * inv * g2 + t2;
            v.w = (a[3] - mu) * inv * g3 + t3;
            *(float4*)&g_ln[lo + (size_t)(re + s) * 64 + 4 * tx] = v;
        }
    }
}

// ---------------- K4: MLP + masked word mean, register accumulators ----------------
__global__ __launch_bounds__(256, 3) void k_mlp(const int* __restrict__ inputs,
                                                const float* __restrict__ W1,
                                                const float* __restrict__ b1,
                                                const float* __restrict__ W2,
                                                const float* __restrict__ b2) {
    __shared__ float W1s[512];        // [o][h]
    __shared__ float b1s[64];
    __shared__ float W2t[64][32];     // W2^T: W2t[o][p]
    __shared__ float b2s[32];
    __shared__ float part[4][64][33]; // [lg][d][p]
    __shared__ int toks[64];
    int b = blockIdx.x, t = threadIdx.x;
    if (t < 64) { toks[t] = inputs[b * 64 + t]; b1s[t] = b1[t]; }
    if (t < 32) b2s[t] = b2[t];
    for (int i = t; i < 512; i += 256) W1s[i] = W1[i];
    for (int i = t; i < 2048; i += 256) {
        int o = i >> 5, p = i & 31;
        W2t[o][p] = W2[p * 64 + o];
    }
    __syncthreads();
    float cnt = 0.f;
    for (int m = 0; m < 64; m++) cnt += (toks[m] != 0) ? 1.f : 0.f;

    int d = t & 63, lg = t >> 6;
    float acc[32];
#pragma unroll
    for (int p = 0; p < 32; p++) acc[p] = 0.f;
#pragma unroll 1
    for (int oc = 0; oc < 4; oc++) {
        float hs[16];
#pragma unroll
        for (int o2 = 0; o2 < 16; o2++) hs[o2] = 0.f;
        for (int li = 0; li < 16; li++) {
            int l = lg * 16 + li;
            if (toks[l] == 0) continue;
            float ft[8];
#pragma unroll
            for (int hh = 0; hh < 8; hh++)
                ft[hh] = g_ln[(((size_t)b * 8 + hh) * 64 + l) * 64 + d];
#pragma unroll
            for (int o2 = 0; o2 < 16; o2++) {
                int o = oc * 16 + o2;
                float4 wa = *(const float4*)&W1s[o * 8];
                float4 wb = *(const float4*)&W1s[o * 8 + 4];
                float v = b1s[o]
                        + wa.x * ft[0] + wa.y * ft[1] + wa.z * ft[2] + wa.w * ft[3]
                        + wb.x * ft[4] + wb.y * ft[5] + wb.z * ft[6] + wb.w * ft[7];
                hs[o2] += fmaxf(v, 0.f);
            }
        }
#pragma unroll
        for (int o2 = 0; o2 < 16; o2++) {
            int o = oc * 16 + o2;
            float hv = hs[o2];
#pragma unroll
            for (int q = 0; q < 8; q++) {
                float4 w = *(const float4*)&W2t[o][4 * q];
                acc[4 * q + 0] += w.x * hv;
                acc[4 * q + 1] += w.y * hv;
                acc[4 * q + 2] += w.z * hv;
                acc[4 * q + 3] += w.w * hv;
            }
        }
    }
#pragma unroll
    for (int p = 0; p < 32; p++) part[lg][d][p] = acc[p];
    __syncthreads();
    float invc = 1.0f / cnt;
    for (int f = t; f < 2048; f += 256) {
        int dd = f >> 5, p = f & 31;
        float w = part[0][dd][p] + part[1][dd][p] + part[2][dd][p] + part[3][dd][p];
        g_word[(size_t)b * 2048 + f] = w * invc + b2s[p];
    }
}

// ---------------- K5: name mean over n_words ----------------
__global__ __launch_bounds__(256) void k_name(float* __restrict__ out, int n_words, int total) {
    int idx = blockIdx.x * 256 + threadIdx.x;
    if (idx >= total) return;
    int g = idx >> 11, f = idx & 2047;
    float s = 0.f;
    for (int w = 0; w < n_words; w++)
        s += g_word[(size_t)(g * n_words + w) * 2048 + f];
    out[idx] = s / (float)n_words;
}

// ---------------- launch ----------------
extern "C" void kernel_launch(void* const* d_in, const int* in_sizes, int n_in,
                              void* d_out, int out_size) {
    const int* inputs  = (const int*)d_in[0];
    const float* W_emb = (const float*)d_in[1];
    const float* W_qkv = (const float*)d_in[2];
    const float* W_pos = (const float*)d_in[3];
    const float* ln_g  = (const float*)d_in[4];
    const float* ln_b  = (const float*)d_in[5];
    const float* W1    = (const float*)d_in[6];
    const float* b1    = (const float*)d_in[7];
    const float* W2    = (const float*)d_in[8];
    const float* b2    = (const float*)d_in[9];

    int B = in_sizes[0] / 64;                         // 2048
    int V = in_sizes[1] / 64;                         // 4096
    int n_words = (int)(((long long)B * 2048) / out_size);

    k_qkv<<<dim3(24, V / 64), 128>>>(W_emb, W_qkv);
    k_mtab<<<1024, 256>>>(W_pos);
    k_sim<<<dim3(NH, B), 128>>>(inputs);
    k_pos_softmax<<<dim3(64, (B * NH) / 64), 128>>>();
    k_av_ln<<<dim3(NH, B), 128>>>(inputs, ln_g, ln_b);
    k_mlp<<<B, 256>>>(inputs, W1, b1, W2, b2);
    k_name<<<(out_size + 255) / 256, 256>>>((float*)d_out, n_words, out_size);
}

// round 7
// speedup vs baseline: 4.5296x; 1.0805x over previous
#include <cuda_runtime.h>
#include <math.h>

#define NH 8

// ---------------- scratch (static __device__, no allocation) ----------------
__device__ float g_qkv[4096 * 24 * 64];          // [v][jh][d], jh: 0-7 q, 8-15 k, 16-23 v
__device__ float g_M[64 * 64 * 64];              // [l][m'][m]
__device__ float g_S[2048 * 8 * 64 * 64];        // [b*H+h][l][m] : sim -> attn (in place)
__device__ float g_ln[2048 * 8 * 64 * 64];       // [b][h][l][d]
__device__ float g_word[2048 * 2048];            // [b][f]

typedef unsigned long long u64;

__device__ __forceinline__ void fma2(u64& d, u64 a, u64 b) {
    asm("fma.rn.f32x2 %0, %1, %2, %3;" : "=l"(d) : "l"(a), "l"(b), "l"(d));
}
__device__ __forceinline__ u64 pk2(float lo, float hi) {
    u64 r; asm("mov.b64 %0, {%1, %2};" : "=l"(r) : "f"(lo), "f"(hi)); return r;
}
__device__ __forceinline__ float2 up2(u64 v) {
    float2 r; asm("mov.b64 {%0, %1}, %2;" : "=f"(r.x), "=f"(r.y) : "l"(v)); return r;
}

// XOR swizzle on the row index of transposed-store arrays: phys = r ^ 8*(k>>3).
// Const-folds in unrolled loops; preserves 16B/32B alignment (only bits >= 8 flip).
#define SWZ(k) (((k) >> 3) << 3)

// 8 rows x 4 cols per thread, f32x2. A [k][r] (ASW: swizzled rows),
// B [k][m] (BSW: swizzled cols or 0). 3 LDS + 4 MOV + 16 FFMA2 per k.
#define GEMM8x4(acc2, Asm, Bsm, ty, tx, ASW, BSW)                      \
    _Pragma("unroll") for (int k_ = 0; k_ < 64; k_++) {                \
        int sa_ = (ASW) ? SWZ(k_) : 0, sb_ = (BSW) ? SWZ(k_) : 0;      \
        ulonglong2 aA = *(const ulonglong2*)&Asm[k_][(8 * (ty)) ^ sa_];\
        ulonglong2 aB = *(const ulonglong2*)&Asm[k_][((8 * (ty)) ^ sa_) + 4];\
        float4 bv = *(const float4*)&Bsm[k_][(4 * (tx)) ^ sb_];        \
        u64 b0 = pk2(bv.x, bv.x), b1 = pk2(bv.y, bv.y);                \
        u64 b2 = pk2(bv.z, bv.z), b3 = pk2(bv.w, bv.w);                \
        fma2(acc2[0][0], aA.x, b0); fma2(acc2[0][1], aA.x, b1);        \
        fma2(acc2[0][2], aA.x, b2); fma2(acc2[0][3], aA.x, b3);        \
        fma2(acc2[1][0], aA.y, b0); fma2(acc2[1][1], aA.y, b1);        \
        fma2(acc2[1][2], aA.y, b2); fma2(acc2[1][3], aA.y, b3);        \
        fma2(acc2[2][0], aB.x, b0); fma2(acc2[2][1], aB.x, b1);        \
        fma2(acc2[2][2], aB.x, b2); fma2(acc2[2][3], aB.x, b3);        \
        fma2(acc2[3][0], aB.y, b0); fma2(acc2[3][1], aB.y, b1);        \
        fma2(acc2[3][2], aB.y, b2); fma2(acc2[3][3], aB.y, b3);        \
    }

// transposed store of a float4 (row r, cols k0..k0+3) into swizzled [k][r] array
#define TSTORE4(Arr, r, k0, v)                                         \
    do {                                                               \
        Arr[(k0) + 0][(r) ^ SWZ((k0) + 0)] = v.x;                      \
        Arr[(k0) + 1][(r) ^ SWZ((k0) + 1)] = v.y;                      \
        Arr[(k0) + 2][(r) ^ SWZ((k0) + 2)] = v.z;                      \
        Arr[(k0) + 3][(r) ^ SWZ((k0) + 3)] = v.w;                      \
    } while (0)

// ---------------- K0a: qkv table = W_emb @ W_qkv^T ----------------
__global__ __launch_bounds__(128) void k_qkv(const float* __restrict__ W_emb,
                                             const float* __restrict__ W_qkv) {
    __shared__ float As[64][64];   // emb^T swz : As[k][v]
    __shared__ float Bs[64][64];   // Wqkv^T swz: Bs[k][r]
    int v0 = blockIdx.y * 64, r0 = blockIdx.x * 64;
    int t = threadIdx.x;
    for (int i = t; i < 1024; i += 128) {
        int row = i >> 4, k0 = (i & 15) * 4;
        float4 e = *(const float4*)&W_emb[(size_t)(v0 + row) * 64 + k0];
        TSTORE4(As, row, k0, e);
        float4 w = *(const float4*)&W_qkv[(size_t)(r0 + row) * 64 + k0];
        TSTORE4(Bs, row, k0, w);
    }
    __syncthreads();
    int tx = t & 15, ty = t >> 4;
    u64 acc2[4][4] = {};
    GEMM8x4(acc2, As, Bs, ty, tx, 1, 1);
#pragma unroll
    for (int p = 0; p < 4; p++) {
        float2 c0 = up2(acc2[p][0]), c1 = up2(acc2[p][1]);
        float2 c2 = up2(acc2[p][2]), c3 = up2(acc2[p][3]);
        int re = 8 * ty + 2 * p;
        *(float4*)&g_qkv[(size_t)(v0 + re) * 1536 + r0 + 4 * tx] =
            make_float4(c0.x, c1.x, c2.x, c3.x);
        *(float4*)&g_qkv[(size_t)(v0 + re + 1) * 1536 + r0 + 4 * tx] =
            make_float4(c0.y, c1.y, c2.y, c3.y);
    }
}

// ---------------- K0b: fused position table ----------------
__global__ __launch_bounds__(256) void k_mtab(const float* __restrict__ W_pos) {
    int idx = blockIdx.x * 256 + threadIdx.x;     // l*4096 + mp*64 + m
    int l = idx >> 12, mp = (idx >> 6) & 63, m = idx & 63;
    float base = (float)(m - l) * (6.283185307179586f / 63.0f);
    float acc = 0.f;
    for (int i = 0; i < 31; i++) {
        float s, c;
        sincosf((float)(i + 1) * base, &s, &c);
        acc += W_pos[i * 64 + mp] * c + W_pos[(i + 31) * 64 + mp] * s;
    }
    g_M[idx] = acc * (1.0f / 62.0f);
}

// ---------------- K1: sim = Q K^T / sqrt(D), key-pad masked ----------------
__global__ __launch_bounds__(128) void k_sim(const int* __restrict__ inputs) {
    __shared__ float Qt[64][64];   // Q^T swz: Qt[d][l]
    __shared__ float Kt[64][64];   // K^T swz: Kt[d][m]
    int h = blockIdx.x, b = blockIdx.y, t = threadIdx.x;
    for (int i = t; i < 1024; i += 128) {
        int m = i >> 4, d0 = (i & 15) * 4;
        int tok = inputs[b * 64 + m];
        size_t base = (size_t)tok * 1536 + h * 64 + d0;
        float4 q = *(const float4*)&g_qkv[base];
        TSTORE4(Qt, m, d0, q);
        float4 kv = *(const float4*)&g_qkv[base + 512];
        TSTORE4(Kt, m, d0, kv);
    }
    __syncthreads();
    int tx = t & 15, ty = t >> 4;
    u64 acc2[4][4] = {};
    GEMM8x4(acc2, Qt, Kt, ty, tx, 1, 1);
    int msk[4];
#pragma unroll
    for (int j = 0; j < 4; j++) msk[j] = (inputs[b * 64 + 4 * tx + j] == 0);
    size_t off = (size_t)(b * NH + h) * 4096;
#pragma unroll
    for (int p = 0; p < 4; p++) {
        float2 c0 = up2(acc2[p][0]), c1 = up2(acc2[p][1]);
        float2 c2 = up2(acc2[p][2]), c3 = up2(acc2[p][3]);
        int re = 8 * ty + 2 * p;
        float4 ve, vo;
        ve.x = msk[0] ? -1e9f : c0.x * 0.125f;  vo.x = msk[0] ? -1e9f : c0.y * 0.125f;
        ve.y = msk[1] ? -1e9f : c1.x * 0.125f;  vo.y = msk[1] ? -1e9f : c1.y * 0.125f;
        ve.z = msk[2] ? -1e9f : c2.x * 0.125f;  vo.z = msk[2] ? -1e9f : c2.y * 0.125f;
        ve.w = msk[3] ? -1e9f : c3.x * 0.125f;  vo.w = msk[3] ? -1e9f : c3.y * 0.125f;
        *(float4*)&g_S[off + (size_t)re * 64 + 4 * tx] = ve;
        *(float4*)&g_S[off + (size_t)(re + 1) * 64 + 4 * tx] = vo;
    }
}

// ---------------- K2: pos bias (via M[l]) + softmax, in place on g_S ----------------
__global__ __launch_bounds__(128) void k_pos_softmax(const int* __restrict__ inputs) {
    __shared__ float Sct[64][64];           // clipped S^T swz: Sct[mp][r]
    __shared__ float Ms[64][64];            // M[l]: [mp][m] natural
    __shared__ unsigned char mskS[8][64];   // pad mask for the 8 b's of this row group
    int l = blockIdx.x, r0 = blockIdx.y * 64, t = threadIdx.x;
    int b0 = r0 >> 3;
    for (int i = t; i < 1024; i += 128)
        ((float4*)Ms)[i] = ((const float4*)(g_M + (size_t)l * 4096))[i];
    for (int i = t; i < 1024; i += 128) {
        int r = i >> 4, m0 = (i & 15) * 4;
        float4 s = *(const float4*)&g_S[((size_t)(r0 + r) * 64 + l) * 64 + m0];
        float4 c;
        c.x = (s.x > -1e8f) ? s.x : 0.f;
        c.y = (s.y > -1e8f) ? s.y : 0.f;
        c.z = (s.z > -1e8f) ? s.z : 0.f;
        c.w = (s.w > -1e8f) ? s.w : 0.f;
        TSTORE4(Sct, r, m0, c);
    }
    for (int i = t; i < 512; i += 128)
        mskS[i >> 6][i & 63] = (inputs[(b0 + (i >> 6)) * 64 + (i & 63)] == 0);
    __syncthreads();
    int tx = t & 15, ty = t >> 4;
    // init acc with raw scores reconstructed from smem (masked cols were -1e9 raw)
    u64 acc2[4][4];
#pragma unroll
    for (int j = 0; j < 4; j++) {
        int m = 4 * tx + j;
        int mk = mskS[ty][m];        // thread's 8 rows share one b (ty-aligned)
        int sw = SWZ(m);
#pragma unroll
        for (int p = 0; p < 4; p++) {
            int re = 8 * ty + 2 * p;
            float lo = mk ? -1e9f : Sct[m][re ^ sw];
            float hi = mk ? -1e9f : Sct[m][(re + 1) ^ sw];
            acc2[p][j] = pk2(lo, hi);
        }
    }
    GEMM8x4(acc2, Sct, Ms, ty, tx, 1, 0);     // acc = s + bias = z
#pragma unroll
    for (int p = 0; p < 4; p++) {
        float2 c0 = up2(acc2[p][0]), c1 = up2(acc2[p][1]);
        float2 c2 = up2(acc2[p][2]), c3 = up2(acc2[p][3]);
        float ze[4] = {c0.x, c1.x, c2.x, c3.x};
        float zo[4] = {c0.y, c1.y, c2.y, c3.y};
        int re = 8 * ty + 2 * p;
#pragma unroll
        for (int s = 0; s < 2; s++) {
            float* z = s ? zo : ze;
            float mx = fmaxf(fmaxf(z[0], z[1]), fmaxf(z[2], z[3]));
#pragma unroll
            for (int d = 1; d < 16; d <<= 1)
                mx = fmaxf(mx, __shfl_xor_sync(0xffffffffu, mx, d));
            float e[4], sm = 0.f;
#pragma unroll
            for (int j = 0; j < 4; j++) { e[j] = __expf(z[j] - mx); sm += e[j]; }
#pragma unroll
            for (int d = 1; d < 16; d <<= 1)
                sm += __shfl_xor_sync(0xffffffffu, sm, d);
            float inv = 1.0f / sm;
            float4 v = make_float4(e[0] * inv, e[1] * inv, e[2] * inv, e[3] * inv);
            *(float4*)&g_S[((size_t)(r0 + re + s) * 64 + l) * 64 + 4 * tx] = v;
        }
    }
}

// ---------------- K3: out = attn @ V, then layernorm over D ----------------
__global__ __launch_bounds__(128) void k_av_ln(const int* __restrict__ inputs,
                                               const float* __restrict__ ln_g,
                                               const float* __restrict__ ln_b) {
    __shared__ float Att[64][64];  // attn^T swz: Att[m][l]
    __shared__ float Vs[64][64];   // V natural: Vs[m][d]
    int h = blockIdx.x, b = blockIdx.y, t = threadIdx.x;
    size_t soff = (size_t)(b * NH + h) * 4096;
    for (int i = t; i < 1024; i += 128) {
        int l = i >> 4, m0 = (i & 15) * 4;
        float4 a = *(const float4*)&g_S[soff + (size_t)l * 64 + m0];
        TSTORE4(Att, l, m0, a);
    }
    for (int i = t; i < 1024; i += 128) {
        int m = i >> 4, d0 = (i & 15) * 4;
        int tok = inputs[b * 64 + m];
        *(float4*)&Vs[m][d0] =
            *(const float4*)&g_qkv[(size_t)tok * 1536 + (2 * NH + h) * 64 + d0];
    }
    __syncthreads();
    int tx = t & 15, ty = t >> 4;
    u64 acc2[4][4] = {};
    GEMM8x4(acc2, Att, Vs, ty, tx, 1, 0);
    float g0 = ln_g[4 * tx + 0], g1 = ln_g[4 * tx + 1], g2 = ln_g[4 * tx + 2], g3 = ln_g[4 * tx + 3];
    float t0 = ln_b[4 * tx + 0], t1 = ln_b[4 * tx + 1], t2 = ln_b[4 * tx + 2], t3 = ln_b[4 * tx + 3];
    size_t lo = (size_t)(b * NH + h) * 4096;
#pragma unroll
    for (int p = 0; p < 4; p++) {
        float2 c0 = up2(acc2[p][0]), c1 = up2(acc2[p][1]);
        float2 c2 = up2(acc2[p][2]), c3 = up2(acc2[p][3]);
        float ae[4] = {c0.x, c1.x, c2.x, c3.x};
        float ao[4] = {c0.y, c1.y, c2.y, c3.y};
        int re = 8 * ty + 2 * p;
#pragma unroll
        for (int s = 0; s < 2; s++) {
            float* a = s ? ao : ae;
            float sm = a[0] + a[1] + a[2] + a[3];
            float sq = a[0] * a[0] + a[1] * a[1] + a[2] * a[2] + a[3] * a[3];
#pragma unroll
            for (int d = 1; d < 16; d <<= 1) {
                sm += __shfl_xor_sync(0xffffffffu, sm, d);
                sq += __shfl_xor_sync(0xffffffffu, sq, d);
            }
            float mu = sm * (1.0f / 64.0f);
            float var = sq * (1.0f / 64.0f) - mu * mu;
            float inv = rsqrtf(var + 1e-5f);
            float4 v;
            v.x = (a[0] - mu) * inv * g0 + t0;
            v.y = (a[1] - mu) * inv * g1 + t1;
            v.z = (a[2] - mu) * inv * g2 + t2;
            v.w = (a[3] - mu) * inv * g3 + t3;
            *(float4*)&g_ln[lo + (size_t)(re + s) * 64 + 4 * tx] = v;
        }
    }
}

// ---------------- K4: MLP + masked word mean, f32x2 o-pairs ----------------
__global__ __launch_bounds__(256, 3) void k_mlp(const int* __restrict__ inputs,
                                                const float* __restrict__ W1,
                                                const float* __restrict__ b1,
                                                const float* __restrict__ W2,
                                                const float* __restrict__ b2) {
    __shared__ u64 W1p[8][32];        // (W1[2op][h], W1[2op+1][h])
    __shared__ float b1s[64];
    __shared__ float W2t[64][32];     // W2^T: W2t[o][p]
    __shared__ float b2s[32];
    __shared__ float part[4][64][33]; // [lg][d][p]
    __shared__ int toks[64];
    int b = blockIdx.x, t = threadIdx.x;
    if (t < 64) { toks[t] = inputs[b * 64 + t]; b1s[t] = b1[t]; }
    if (t < 32) b2s[t] = b2[t];
    {
        int op = t & 31, h = t >> 5;
        if (t < 256) W1p[h][op] = pk2(W1[(2 * op) * 8 + h], W1[(2 * op + 1) * 8 + h]);
    }
    for (int i = t; i < 2048; i += 256) {
        int o = i >> 5, p = i & 31;
        W2t[o][p] = W2[p * 64 + o];
    }
    __syncthreads();
    float cnt = 0.f;
    for (int m = 0; m < 64; m++) cnt += (toks[m] != 0) ? 1.f : 0.f;

    int d = t & 63, lg = t >> 6;
    u64 acc2[16];                     // packed over p pairs, persistent
#pragma unroll
    for (int q = 0; q < 16; q++) acc2[q] = 0ull;
#pragma unroll 1
    for (int oc = 0; oc < 4; oc++) {
        float hs[16];
#pragma unroll
        for (int o2 = 0; o2 < 16; o2++) hs[o2] = 0.f;
        for (int li = 0; li < 16; li++) {
            int l = lg * 16 + li;
            if (toks[l] == 0) continue;
            u64 ftd[8];
#pragma unroll
            for (int hh = 0; hh < 8; hh++) {
                float f = g_ln[(((size_t)b * 8 + hh) * 64 + l) * 64 + d];
                ftd[hh] = pk2(f, f);
            }
#pragma unroll
            for (int pi = 0; pi < 8; pi++) {
                int opair = oc * 8 + pi;                // o = 2*opair, 2*opair+1
                u64 v2 = *(const u64*)&b1s[2 * opair];
#pragma unroll
                for (int hh = 0; hh < 8; hh++)
                    fma2(v2, ftd[hh], W1p[hh][opair]);
                float2 vv = up2(v2);
                hs[2 * pi]     += fmaxf(vv.x, 0.f);
                hs[2 * pi + 1] += fmaxf(vv.y, 0.f);
            }
        }
#pragma unroll
        for (int o2 = 0; o2 < 16; o2++) {
            int o = oc * 16 + o2;
            u64 hv2 = pk2(hs[o2], hs[o2]);
#pragma unroll
            for (int q = 0; q < 16; q++)
                fma2(acc2[q], hv2, *(const u64*)&W2t[o][2 * q]);
        }
    }
#pragma unroll
    for (int q = 0; q < 16; q++) {
        float2 v = up2(acc2[q]);
        part[lg][d][2 * q] = v.x;
        part[lg][d][2 * q + 1] = v.y;
    }
    __syncthreads();
    float invc = 1.0f / cnt;
    for (int f = t; f < 2048; f += 256) {
        int dd = f >> 5, p = f & 31;
        float w = part[0][dd][p] + part[1][dd][p] + part[2][dd][p] + part[3][dd][p];
        g_word[(size_t)b * 2048 + f] = w * invc + b2s[p];
    }
}

// ---------------- K5: name mean over n_words ----------------
__global__ __launch_bounds__(256) void k_name(float* __restrict__ out, int n_words, int total) {
    int idx = blockIdx.x * 256 + threadIdx.x;
    if (idx >= total) return;
    int g = idx >> 11, f = idx & 2047;
    float s = 0.f;
    for (int w = 0; w < n_words; w++)
        s += g_word[(size_t)(g * n_words + w) * 2048 + f];
    out[idx] = s / (float)n_words;
}

// ---------------- launch ----------------
extern "C" void kernel_launch(void* const* d_in, const int* in_sizes, int n_in,
                              void* d_out, int out_size) {
    const int* inputs  = (const int*)d_in[0];
    const float* W_emb = (const float*)d_in[1];
    const float* W_qkv = (const float*)d_in[2];
    const float* W_pos = (const float*)d_in[3];
    const float* ln_g  = (const float*)d_in[4];
    const float* ln_b  = (const float*)d_in[5];
    const float* W1    = (const float*)d_in[6];
    const float* b1    = (const float*)d_in[7];
    const float* W2    = (const float*)d_in[8];
    const float* b2    = (const float*)d_in[9];

    int B = in_sizes[0] / 64;                         // 2048
    int V = in_sizes[1] / 64;                         // 4096
    int n_words = (int)(((long long)B * 2048) / out_size);

    k_qkv<<<dim3(24, V / 64), 128>>>(W_emb, W_qkv);
    k_mtab<<<1024, 256>>>(W_pos);
    k_sim<<<dim3(NH, B), 128>>>(inputs);
    k_pos_softmax<<<dim3(64, (B * NH) / 64), 128>>>(inputs);
    k_av_ln<<<dim3(NH, B), 128>>>(inputs, ln_g, ln_b);
    k_mlp<<<B, 256>>>(inputs, W1, b1, W2, b2);
    k_name<<<(out_size + 255) / 256, 256>>>((float*)d_out, n_words, out_size);
}

// round 8
// speedup vs baseline: 4.5792x; 1.0109x over previous
#include <cuda_runtime.h>
#include <math.h>

#define NH 8

// ---------------- scratch (static __device__, no allocation) ----------------
__device__ float g_qkv[4096 * 24 * 64];          // [v][jh][d], jh: 0-7 q, 8-15 k, 16-23 v
__device__ float g_M[64 * 64 * 64];              // [l][m'][m]
__device__ float g_S[2048 * 8 * 64 * 64];        // [b*H+h][l][m] : sim -> attn (in place)
__device__ float g_ln[2048 * 8 * 64 * 64];       // [b][h][l][d]
__device__ float g_word[2048 * 2048];            // [b][f]

typedef unsigned long long u64;
typedef unsigned int u32;

__device__ __forceinline__ void fma2(u64& d, u64 a, u64 b) {
    asm("fma.rn.f32x2 %0, %1, %2, %3;" : "=l"(d) : "l"(a), "l"(b), "l"(d));
}
__device__ __forceinline__ u64 pk2(float lo, float hi) {
    u64 r; asm("mov.b64 %0, {%1, %2};" : "=l"(r) : "f"(lo), "f"(hi)); return r;
}
__device__ __forceinline__ float2 up2(u64 v) {
    float2 r; asm("mov.b64 {%0, %1}, %2;" : "=f"(r.x), "=f"(r.y) : "l"(v)); return r;
}

// ---------------- bf16 split helpers ----------------
__device__ __forceinline__ u32 pkbf(float e, float o) {   // e -> low half, o -> high half
    u32 r; asm("cvt.rn.bf16x2.f32 %0, %1, %2;" : "=r"(r) : "f"(o), "f"(e)); return r;
}
__device__ __forceinline__ float bflo(u32 w) { return __uint_as_float(w << 16); }
__device__ __forceinline__ float bfhi(u32 w) { return __uint_as_float(w & 0xffff0000u); }

__device__ __forceinline__ void split_pair(float e, float o, u32& h, u32& l) {
    h = pkbf(e, o);
    l = pkbf(e - bflo(h), o - bfhi(h));
}

// ---------------- fragment-arranged smem stores ----------------
// A frag layout: AH[((w*4+ks)*32+lane)*4 + reg], reg = rsel + 2*hi8
__device__ __forceinline__ void a_store4(u32* AH, u32* AL, int m, int k0, float4 x) {
    int w = m >> 4, r = m & 15;
    int ks = k0 >> 4, kin = k0 & 15;
    int base = ((w * 4 + ks) * 32 + 4 * (r & 7) + ((kin & 7) >> 1)) * 4 + (r >> 3) + ((kin >> 3) << 1);
    u32 h0, l0, h1, l1;
    split_pair(x.x, x.y, h0, l0);
    split_pair(x.z, x.w, h1, l1);
    AH[base] = h0; AL[base] = l0;
    AH[base + 4] = h1; AL[base + 4] = l1;   // next k-pair -> lane+1 -> +4 words
}
// B frag layout: BH[((ks*8+nt)*32+lane)*2 + hi8]
__device__ __forceinline__ void b_store4n(u32* BH, u32* BL, int n, int k0, float4 x) {
    int ks = k0 >> 4, kin = k0 & 15;
    int base = ((ks * 8 + (n >> 3)) * 32 + 4 * (n & 7) + ((kin & 7) >> 1)) * 2 + (kin >> 3);
    u32 h0, l0, h1, l1;
    split_pair(x.x, x.y, h0, l0);
    split_pair(x.z, x.w, h1, l1);
    BH[base] = h0; BL[base] = l0;
    BH[base + 2] = h1; BL[base + 2] = l1;
}
// B from k-major source: rows k (even) and k+1, cols n0..n0+3
__device__ __forceinline__ void b_store4k(u32* BH, u32* BL, int k, int n0, float4 ev, float4 od) {
    int ks = k >> 4, kin = k & 15;
    int tig = (kin & 7) >> 1, hi8 = kin >> 3;
    float e[4] = {ev.x, ev.y, ev.z, ev.w};
    float o[4] = {od.x, od.y, od.z, od.w};
#pragma unroll
    for (int j = 0; j < 4; j++) {
        int n = n0 + j;
        int base = ((ks * 8 + (n >> 3)) * 32 + 4 * (n & 7) + tig) * 2 + hi8;
        u32 h, l;
        split_pair(e[j], o[j], h, l);
        BH[base] = h; BL[base] = l;
    }
}

__device__ __forceinline__ void mma_bf16(float* c, const u32* a, const u32* b) {
    asm volatile("mma.sync.aligned.m16n8k16.row.col.f32.bf16.bf16.f32 "
                 "{%0,%1,%2,%3}, {%4,%5,%6,%7}, {%8,%9}, {%0,%1,%2,%3};"
                 : "+f"(c[0]), "+f"(c[1]), "+f"(c[2]), "+f"(c[3])
                 : "r"(a[0]), "r"(a[1]), "r"(a[2]), "r"(a[3]), "r"(b[0]), "r"(b[1]));
}

// full 64x64x64 GEMM, warp w: rows 16w..16w+15, 8 n-tiles; 3-term split bf16
#define MMA_GEMM(c, AH, AL, BH, BL, w, lane)                               \
    _Pragma("unroll") for (int ks_ = 0; ks_ < 4; ks_++) {                  \
        uint4 ah_ = *(const uint4*)&AH[(((w) * 4 + ks_) * 32 + (lane)) * 4]; \
        uint4 al_ = *(const uint4*)&AL[(((w) * 4 + ks_) * 32 + (lane)) * 4]; \
        _Pragma("unroll") for (int nt_ = 0; nt_ < 8; nt_++) {              \
            uint2 bh_ = *(const uint2*)&BH[((ks_ * 8 + nt_) * 32 + (lane)) * 2]; \
            uint2 bl_ = *(const uint2*)&BL[((ks_ * 8 + nt_) * 32 + (lane)) * 2]; \
            mma_bf16(c[nt_], (const u32*)&ah_, (const u32*)&bh_);          \
            mma_bf16(c[nt_], (const u32*)&ah_, (const u32*)&bl_);          \
            mma_bf16(c[nt_], (const u32*)&al_, (const u32*)&bh_);          \
        }                                                                  \
    }

// ---------------- K0a: qkv table = W_emb @ W_qkv^T ----------------
__global__ __launch_bounds__(128) void k_qkv(const float* __restrict__ W_emb,
                                             const float* __restrict__ W_qkv) {
    __shared__ u32 AH[2048], AL[2048], BH[2048], BL[2048];
    int v0 = blockIdx.y * 64, r0 = blockIdx.x * 64, t = threadIdx.x;
    for (int i = t; i < 1024; i += 128) {
        int row = i >> 4, k0 = (i & 15) * 4;
        a_store4(AH, AL, row, k0, *(const float4*)&W_emb[(size_t)(v0 + row) * 64 + k0]);
        b_store4n(BH, BL, row, k0, *(const float4*)&W_qkv[(size_t)(r0 + row) * 64 + k0]);
    }
    __syncthreads();
    int lane = t & 31, w = t >> 5, grp = lane >> 2, tig = lane & 3;
    float c[8][4] = {};
    MMA_GEMM(c, AH, AL, BH, BL, w, lane);
    int row = v0 + 16 * w + grp;
#pragma unroll
    for (int nt = 0; nt < 8; nt++) {
        int col = r0 + 8 * nt + 2 * tig;
        *(float2*)&g_qkv[(size_t)row * 1536 + col] = make_float2(c[nt][0], c[nt][1]);
        *(float2*)&g_qkv[(size_t)(row + 8) * 1536 + col] = make_float2(c[nt][2], c[nt][3]);
    }
}

// ---------------- K0b: fused position table ----------------
__global__ __launch_bounds__(256) void k_mtab(const float* __restrict__ W_pos) {
    int idx = blockIdx.x * 256 + threadIdx.x;     // l*4096 + mp*64 + m
    int l = idx >> 12, mp = (idx >> 6) & 63, m = idx & 63;
    float base = (float)(m - l) * (6.283185307179586f / 63.0f);
    float acc = 0.f;
    for (int i = 0; i < 31; i++) {
        float s, c;
        sincosf((float)(i + 1) * base, &s, &c);
        acc += W_pos[i * 64 + mp] * c + W_pos[(i + 31) * 64 + mp] * s;
    }
    g_M[idx] = acc * (1.0f / 62.0f);
}

// ---------------- K1: sim = Q K^T / sqrt(D), key-pad masked ----------------
__global__ __launch_bounds__(128) void k_sim(const int* __restrict__ inputs) {
    __shared__ u32 AH[2048], AL[2048], BH[2048], BL[2048];
    int h = blockIdx.x, b = blockIdx.y, t = threadIdx.x;
    for (int i = t; i < 1024; i += 128) {
        int row = i >> 4, k0 = (i & 15) * 4;
        int tok = inputs[b * 64 + row];
        size_t base = (size_t)tok * 1536 + h * 64 + k0;
        a_store4(AH, AL, row, k0, *(const float4*)&g_qkv[base]);           // Q
        b_store4n(BH, BL, row, k0, *(const float4*)&g_qkv[base + 512]);    // K
    }
    __syncthreads();
    int lane = t & 31, w = t >> 5, grp = lane >> 2, tig = lane & 3;
    float c[8][4] = {};
    MMA_GEMM(c, AH, AL, BH, BL, w, lane);
    int row = 16 * w + grp;
    size_t off = (size_t)(b * NH + h) * 4096;
#pragma unroll
    for (int nt = 0; nt < 8; nt++) {
        int col = 8 * nt + 2 * tig;
        int m0 = (inputs[b * 64 + col] == 0);
        int m1 = (inputs[b * 64 + col + 1] == 0);
        float2 ve, vo;
        ve.x = m0 ? -1e9f : c[nt][0] * 0.125f;
        ve.y = m1 ? -1e9f : c[nt][1] * 0.125f;
        vo.x = m0 ? -1e9f : c[nt][2] * 0.125f;
        vo.y = m1 ? -1e9f : c[nt][3] * 0.125f;
        *(float2*)&g_S[off + (size_t)row * 64 + col] = ve;
        *(float2*)&g_S[off + (size_t)(row + 8) * 64 + col] = vo;
    }
}

// ---------------- K2: pos bias (via M[l]) + softmax, in place on g_S ----------------
__global__ __launch_bounds__(128) void k_pos_softmax(const int* __restrict__ inputs) {
    __shared__ u32 AH[2048], AL[2048], BH[2048], BL[2048];  // A = clipped S, B = M[l]
    __shared__ unsigned char mskS[8][64];
    int l = blockIdx.x, r0 = blockIdx.y * 64, t = threadIdx.x;
    int b0 = r0 >> 3;
    for (int i = t; i < 1024; i += 128) {
        int row = i >> 4, m0 = (i & 15) * 4;
        float4 s = *(const float4*)&g_S[((size_t)(r0 + row) * 64 + l) * 64 + m0];
        float4 cl;
        cl.x = (s.x > -1e8f) ? s.x : 0.f;
        cl.y = (s.y > -1e8f) ? s.y : 0.f;
        cl.z = (s.z > -1e8f) ? s.z : 0.f;
        cl.w = (s.w > -1e8f) ? s.w : 0.f;
        a_store4(AH, AL, row, m0, cl);
    }
    for (int i = t; i < 512; i += 128) {
        int kp = i >> 4, n0 = (i & 15) * 4;
        float4 ev = *(const float4*)&g_M[(size_t)l * 4096 + (2 * kp) * 64 + n0];
        float4 od = *(const float4*)&g_M[(size_t)l * 4096 + (2 * kp + 1) * 64 + n0];
        b_store4k(BH, BL, 2 * kp, n0, ev, od);
    }
    for (int i = t; i < 512; i += 128)
        mskS[i >> 6][i & 63] = (inputs[(b0 + (i >> 6)) * 64 + (i & 63)] == 0);
    __syncthreads();
    int lane = t & 31, w = t >> 5, grp = lane >> 2, tig = lane & 3;
    int row = 16 * w + grp;
    int blo = row >> 3, bhi = (row + 8) >> 3;
    // init acc = raw S, reconstructed from own A-fragment words (clip==raw unless masked)
    float c[8][4];
#pragma unroll
    for (int nt = 0; nt < 8; nt++) {
        int ks = nt >> 1, hb = (nt & 1) << 1;
        int ib = ((w * 4 + ks) * 32 + lane) * 4 + hb;
        u32 h0 = AH[ib], l0 = AL[ib];           // rsel 0: row
        u32 h1 = AH[ib + 1], l1 = AL[ib + 1];   // rsel 1: row+8
        int col = 8 * nt + 2 * tig;
        int m0lo = mskS[blo][col], m1lo = mskS[blo][col + 1];
        int m0hi = mskS[bhi][col], m1hi = mskS[bhi][col + 1];
        c[nt][0] = m0lo ? -1e9f : (bflo(h0) + bflo(l0));
        c[nt][1] = m1lo ? -1e9f : (bfhi(h0) + bfhi(l0));
        c[nt][2] = m0hi ? -1e9f : (bflo(h1) + bflo(l1));
        c[nt][3] = m1hi ? -1e9f : (bfhi(h1) + bfhi(l1));
    }
    MMA_GEMM(c, AH, AL, BH, BL, w, lane);   // c = s + bias = z
    size_t base = ((size_t)(r0 + row) * 64 + l) * 64;
#pragma unroll
    for (int s = 0; s < 2; s++) {           // s=0: row, s=1: row+8
        float z[8][2];
#pragma unroll
        for (int nt = 0; nt < 8; nt++) { z[nt][0] = c[nt][2 * s]; z[nt][1] = c[nt][2 * s + 1]; }
        float mx = -3.4e38f;
#pragma unroll
        for (int nt = 0; nt < 8; nt++) mx = fmaxf(mx, fmaxf(z[nt][0], z[nt][1]));
        mx = fmaxf(mx, __shfl_xor_sync(0xffffffffu, mx, 1));
        mx = fmaxf(mx, __shfl_xor_sync(0xffffffffu, mx, 2));
        float e[8][2], sm = 0.f;
#pragma unroll
        for (int nt = 0; nt < 8; nt++) {
            e[nt][0] = __expf(z[nt][0] - mx);
            e[nt][1] = __expf(z[nt][1] - mx);
            sm += e[nt][0] + e[nt][1];
        }
        sm += __shfl_xor_sync(0xffffffffu, sm, 1);
        sm += __shfl_xor_sync(0xffffffffu, sm, 2);
        float inv = 1.0f / sm;
        size_t rb = base + (size_t)s * 8 * 4096;
#pragma unroll
        for (int nt = 0; nt < 8; nt++)
            *(float2*)&g_S[rb + 8 * nt + 2 * tig] = make_float2(e[nt][0] * inv, e[nt][1] * inv);
    }
}

// ---------------- K3: out = attn @ V, then layernorm over D ----------------
__global__ __launch_bounds__(128) void k_av_ln(const int* __restrict__ inputs,
                                               const float* __restrict__ ln_g,
                                               const float* __restrict__ ln_b) {
    __shared__ u32 AH[2048], AL[2048], BH[2048], BL[2048];  // A = attn, B = V (k-major)
    int h = blockIdx.x, b = blockIdx.y, t = threadIdx.x;
    size_t soff = (size_t)(b * NH + h) * 4096;
    for (int i = t; i < 1024; i += 128) {
        int row = i >> 4, m0 = (i & 15) * 4;
        a_store4(AH, AL, row, m0, *(const float4*)&g_S[soff + (size_t)row * 64 + m0]);
    }
    for (int i = t; i < 512; i += 128) {
        int kp = i >> 4, d0 = (i & 15) * 4;
        int te = inputs[b * 64 + 2 * kp], to = inputs[b * 64 + 2 * kp + 1];
        float4 ev = *(const float4*)&g_qkv[(size_t)te * 1536 + (2 * NH + h) * 64 + d0];
        float4 od = *(const float4*)&g_qkv[(size_t)to * 1536 + (2 * NH + h) * 64 + d0];
        b_store4k(BH, BL, 2 * kp, d0, ev, od);
    }
    __syncthreads();
    int lane = t & 31, w = t >> 5, grp = lane >> 2, tig = lane & 3;
    float c[8][4] = {};
    MMA_GEMM(c, AH, AL, BH, BL, w, lane);
    int row = 16 * w + grp;
    size_t lo = (size_t)(b * NH + h) * 4096;
#pragma unroll
    for (int s = 0; s < 2; s++) {
        float a[8][2];
#pragma unroll
        for (int nt = 0; nt < 8; nt++) { a[nt][0] = c[nt][2 * s]; a[nt][1] = c[nt][2 * s + 1]; }
        float sm = 0.f, sq = 0.f;
#pragma unroll
        for (int nt = 0; nt < 8; nt++) {
            sm += a[nt][0] + a[nt][1];
            sq += a[nt][0] * a[nt][0] + a[nt][1] * a[nt][1];
        }
#pragma unroll
        for (int d = 1; d < 4; d <<= 1) {
            sm += __shfl_xor_sync(0xffffffffu, sm, d);
            sq += __shfl_xor_sync(0xffffffffu, sq, d);
        }
        float mu = sm * (1.0f / 64.0f);
        float var = sq * (1.0f / 64.0f) - mu * mu;
        float inv = rsqrtf(var + 1e-5f);
        size_t rb = lo + (size_t)(row + 8 * s) * 64;
#pragma unroll
        for (int nt = 0; nt < 8; nt++) {
            int col = 8 * nt + 2 * tig;
            float2 v;
            v.x = (a[nt][0] - mu) * inv * ln_g[col] + ln_b[col];
            v.y = (a[nt][1] - mu) * inv * ln_g[col + 1] + ln_b[col + 1];
            *(float2*)&g_ln[rb + col] = v;
        }
    }
}

// ---------------- K4: MLP + masked word mean, f32x2 o-pairs ----------------
__global__ __launch_bounds__(256, 3) void k_mlp(const int* __restrict__ inputs,
                                                const float* __restrict__ W1,
                                                const float* __restrict__ b1,
                                                const float* __restrict__ W2,
                                                const float* __restrict__ b2) {
    __shared__ u64 W1p[8][32];        // (W1[2op][h], W1[2op+1][h])
    __shared__ float b1s[64];
    __shared__ float W2t[64][32];     // W2^T: W2t[o][p]
    __shared__ float b2s[32];
    __shared__ float part[4][64][33]; // [lg][d][p]
    __shared__ int toks[64];
    int b = blockIdx.x, t = threadIdx.x;
    if (t < 64) { toks[t] = inputs[b * 64 + t]; b1s[t] = b1[t]; }
    if (t < 32) b2s[t] = b2[t];
    {
        int op = t & 31, hh = t >> 5;
        if (t < 256) W1p[hh][op] = pk2(W1[(2 * op) * 8 + hh], W1[(2 * op + 1) * 8 + hh]);
    }
    for (int i = t; i < 2048; i += 256) {
        int o = i >> 5, p = i & 31;
        W2t[o][p] = W2[p * 64 + o];
    }
    __syncthreads();
    float cnt = 0.f;
    for (int m = 0; m < 64; m++) cnt += (toks[m] != 0) ? 1.f : 0.f;

    int d = t & 63, lg = t >> 6;
    u64 acc2[16];
#pragma unroll
    for (int q = 0; q < 16; q++) acc2[q] = 0ull;
#pragma unroll 1
    for (int oc = 0; oc < 4; oc++) {
        float hs[16];
#pragma unroll
        for (int o2 = 0; o2 < 16; o2++) hs[o2] = 0.f;
        for (int li = 0; li < 16; li++) {
            int l = lg * 16 + li;
            if (toks[l] == 0) continue;
            u64 ftd[8];
#pragma unroll
            for (int hh = 0; hh < 8; hh++) {
                float f = g_ln[(((size_t)b * 8 + hh) * 64 + l) * 64 + d];
                ftd[hh] = pk2(f, f);
            }
#pragma unroll
            for (int pi = 0; pi < 8; pi++) {
                int opair = oc * 8 + pi;
                u64 v2 = *(const u64*)&b1s[2 * opair];
#pragma unroll
                for (int hh = 0; hh < 8; hh++)
                    fma2(v2, ftd[hh], W1p[hh][opair]);
                float2 vv = up2(v2);
                hs[2 * pi]     += fmaxf(vv.x, 0.f);
                hs[2 * pi + 1] += fmaxf(vv.y, 0.f);
            }
        }
#pragma unroll
        for (int o2 = 0; o2 < 16; o2++) {
            int o = oc * 16 + o2;
            u64 hv2 = pk2(hs[o2], hs[o2]);
#pragma unroll
            for (int q = 0; q < 16; q++)
                fma2(acc2[q], hv2, *(const u64*)&W2t[o][2 * q]);
        }
    }
#pragma unroll
    for (int q = 0; q < 16; q++) {
        float2 v = up2(acc2[q]);
        part[lg][d][2 * q] = v.x;
        part[lg][d][2 * q + 1] = v.y;
    }
    __syncthreads();
    float invc = 1.0f / cnt;
    for (int f = t; f < 2048; f += 256) {
        int dd = f >> 5, p = f & 31;
        float w = part[0][dd][p] + part[1][dd][p] + part[2][dd][p] + part[3][dd][p];
        g_word[(size_t)b * 2048 + f] = w * invc + b2s[p];
    }
}

// ---------------- K5: name mean over n_words ----------------
__global__ __launch_bounds__(256) void k_name(float* __restrict__ out, int n_words, int total) {
    int idx = blockIdx.x * 256 + threadIdx.x;
    if (idx >= total) return;
    int g = idx >> 11, f = idx & 2047;
    float s = 0.f;
    for (int w = 0; w < n_words; w++)
        s += g_word[(size_t)(g * n_words + w) * 2048 + f];
    out[idx] = s / (float)n_words;
}

// ---------------- launch ----------------
extern "C" void kernel_launch(void* const* d_in, const int* in_sizes, int n_in,
                              void* d_out, int out_size) {
    const int* inputs  = (const int*)d_in[0];
    const float* W_emb = (const float*)d_in[1];
    const float* W_qkv = (const float*)d_in[2];
    const float* W_pos = (const float*)d_in[3];
    const float* ln_g  = (const float*)d_in[4];
    const float* ln_b  = (const float*)d_in[5];
    const float* W1    = (const float*)d_in[6];
    const float* b1    = (const float*)d_in[7];
    const float* W2    = (const float*)d_in[8];
    const float* b2    = (const float*)d_in[9];

    int B = in_sizes[0] / 64;                         // 2048
    int V = in_sizes[1] / 64;                         // 4096
    int n_words = (int)(((long long)B * 2048) / out_size);

    k_qkv<<<dim3(24, V / 64), 128>>>(W_emb, W_qkv);
    k_mtab<<<1024, 256>>>(W_pos);
    k_sim<<<dim3(NH, B), 128>>>(inputs);
    k_pos_softmax<<<dim3(64, (B * NH) / 64), 128>>>(inputs);
    k_av_ln<<<dim3(NH, B), 128>>>(inputs, ln_g, ln_b);
    k_mlp<<<B, 256>>>(inputs, W1, b1, W2, b2);
    k_name<<<(out_size + 255) / 256, 256>>>((float*)d_out, n_words, out_size);
}

// round 9
// speedup vs baseline: 5.8547x; 1.2785x over previous
#include <cuda_runtime.h>
#include <math.h>

#define NH 8

// ---------------- scratch (static __device__, no allocation) ----------------
__device__ float g_qkv[4096 * 24 * 64];          // [v][jh][d], jh: 0-7 q, 8-15 k, 16-23 v
__device__ float g_ln[2048 * 8 * 64 * 64];       // [b][h][l][d]
__device__ float g_word[2048 * 2048];            // [b][f]
// const tables (built by k_const each launch)
__device__ unsigned int g_B2h[2048], g_B2l[2048];    // W_pos interleaved, B-frag split
__device__ unsigned int g_B3h[2048], g_B3l[2048];    // cos/sin table, B-frag split
__device__ float2 g_rotc[2048];                      // [l][q] (cos(a_q l)/62, sin(a_q l)/62)

typedef unsigned long long u64;
typedef unsigned int u32;

__device__ __forceinline__ void fma2(u64& d, u64 a, u64 b) {
    asm("fma.rn.f32x2 %0, %1, %2, %3;" : "=l"(d) : "l"(a), "l"(b), "l"(d));
}
__device__ __forceinline__ u64 pk2(float lo, float hi) {
    u64 r; asm("mov.b64 %0, {%1, %2};" : "=l"(r) : "f"(lo), "f"(hi)); return r;
}
__device__ __forceinline__ float2 up2(u64 v) {
    float2 r; asm("mov.b64 {%0, %1}, %2;" : "=f"(r.x), "=f"(r.y) : "l"(v)); return r;
}

// ---------------- bf16 split helpers ----------------
__device__ __forceinline__ u32 pkbf(float e, float o) {   // e -> low half, o -> high half
    u32 r; asm("cvt.rn.bf16x2.f32 %0, %1, %2;" : "=r"(r) : "f"(o), "f"(e)); return r;
}
__device__ __forceinline__ float bflo(u32 w) { return __uint_as_float(w << 16); }
__device__ __forceinline__ float bfhi(u32 w) { return __uint_as_float(w & 0xffff0000u); }
__device__ __forceinline__ void split_pair(float e, float o, u32& h, u32& l) {
    h = pkbf(e, o);
    l = pkbf(e - bflo(h), o - bfhi(h));
}

// ---------------- fragment-arranged smem stores (validated R8) ----------------
__device__ __forceinline__ void a_store4(u32* AH, u32* AL, int m, int k0, float4 x) {
    int w = m >> 4, r = m & 15;
    int ks = k0 >> 4, kin = k0 & 15;
    int base = ((w * 4 + ks) * 32 + 4 * (r & 7) + ((kin & 7) >> 1)) * 4 + (r >> 3) + ((kin >> 3) << 1);
    u32 h0, l0, h1, l1;
    split_pair(x.x, x.y, h0, l0);
    split_pair(x.z, x.w, h1, l1);
    AH[base] = h0; AL[base] = l0;
    AH[base + 4] = h1; AL[base + 4] = l1;
}
__device__ __forceinline__ void b_store4n(u32* BH, u32* BL, int n, int k0, float4 x) {
    int ks = k0 >> 4, kin = k0 & 15;
    int base = ((ks * 8 + (n >> 3)) * 32 + 4 * (n & 7) + ((kin & 7) >> 1)) * 2 + (kin >> 3);
    u32 h0, l0, h1, l1;
    split_pair(x.x, x.y, h0, l0);
    split_pair(x.z, x.w, h1, l1);
    BH[base] = h0; BL[base] = l0;
    BH[base + 2] = h1; BL[base + 2] = l1;
}
__device__ __forceinline__ void b_store4k(u32* BH, u32* BL, int k, int n0, float4 ev, float4 od) {
    int ks = k >> 4, kin = k & 15;
    int tig = (kin & 7) >> 1, hi8 = kin >> 3;
    float e[4] = {ev.x, ev.y, ev.z, ev.w};
    float o[4] = {od.x, od.y, od.z, od.w};
#pragma unroll
    for (int j = 0; j < 4; j++) {
        int n = n0 + j;
        int base = ((ks * 8 + (n >> 3)) * 32 + 4 * (n & 7) + tig) * 2 + hi8;
        u32 h, l;
        split_pair(e[j], o[j], h, l);
        BH[base] = h; BL[base] = l;
    }
}

__device__ __forceinline__ void mma_bf16(float* c, const u32* a, const u32* b) {
    asm volatile("mma.sync.aligned.m16n8k16.row.col.f32.bf16.bf16.f32 "
                 "{%0,%1,%2,%3}, {%4,%5,%6,%7}, {%8,%9}, {%0,%1,%2,%3};"
                 : "+f"(c[0]), "+f"(c[1]), "+f"(c[2]), "+f"(c[3])
                 : "r"(a[0]), "r"(a[1]), "r"(a[2]), "r"(a[3]), "r"(b[0]), "r"(b[1]));
}

// full 64x64x64 GEMM from smem operands (validated R8)
#define MMA_GEMM(c, AH, AL, BH, BL, w, lane)                               \
    _Pragma("unroll") for (int ks_ = 0; ks_ < 4; ks_++) {                  \
        uint4 ah_ = *(const uint4*)&AH[(((w) * 4 + ks_) * 32 + (lane)) * 4]; \
        uint4 al_ = *(const uint4*)&AL[(((w) * 4 + ks_) * 32 + (lane)) * 4]; \
        _Pragma("unroll") for (int nt_ = 0; nt_ < 8; nt_++) {              \
            uint2 bh_ = *(const uint2*)&BH[((ks_ * 8 + nt_) * 32 + (lane)) * 2]; \
            uint2 bl_ = *(const uint2*)&BL[((ks_ * 8 + nt_) * 32 + (lane)) * 2]; \
            mma_bf16(c[nt_], (const u32*)&ah_, (const u32*)&bh_);          \
            mma_bf16(c[nt_], (const u32*)&ah_, (const u32*)&bl_);          \
            mma_bf16(c[nt_], (const u32*)&al_, (const u32*)&bh_);          \
        }                                                                  \
    }

// in-register C-fragment (tiles nt0, nt1) -> split A-fragment for k-chunk
__device__ __forceinline__ void c2a(const float* c0, const float* c1, u32* ah, u32* al) {
    ah[0] = pkbf(c0[0], c0[1]); al[0] = pkbf(c0[0] - bflo(ah[0]), c0[1] - bfhi(ah[0]));
    ah[1] = pkbf(c0[2], c0[3]); al[1] = pkbf(c0[2] - bflo(ah[1]), c0[3] - bfhi(ah[1]));
    ah[2] = pkbf(c1[0], c1[1]); al[2] = pkbf(c1[0] - bflo(ah[2]), c1[1] - bfhi(ah[2]));
    ah[3] = pkbf(c1[2], c1[3]); al[3] = pkbf(c1[2] - bflo(ah[3]), c1[3] - bfhi(ah[3]));
}

// ---------------- K0a: qkv table = W_emb @ W_qkv^T (unchanged, validated) ----------------
__global__ __launch_bounds__(128) void k_qkv(const float* __restrict__ W_emb,
                                             const float* __restrict__ W_qkv) {
    __shared__ u32 AH[2048], AL[2048], BH[2048], BL[2048];
    int v0 = blockIdx.y * 64, r0 = blockIdx.x * 64, t = threadIdx.x;
    for (int i = t; i < 1024; i += 128) {
        int row = i >> 4, k0 = (i & 15) * 4;
        a_store4(AH, AL, row, k0, *(const float4*)&W_emb[(size_t)(v0 + row) * 64 + k0]);
        b_store4n(BH, BL, row, k0, *(const float4*)&W_qkv[(size_t)(r0 + row) * 64 + k0]);
    }
    __syncthreads();
    int lane = t & 31, w = t >> 5, grp = lane >> 2, tig = lane & 3;
    float c[8][4] = {};
    MMA_GEMM(c, AH, AL, BH, BL, w, lane);
    int row = v0 + 16 * w + grp;
#pragma unroll
    for (int nt = 0; nt < 8; nt++) {
        int col = r0 + 8 * nt + 2 * tig;
        *(float2*)&g_qkv[(size_t)row * 1536 + col] = make_float2(c[nt][0], c[nt][1]);
        *(float2*)&g_qkv[(size_t)(row + 8) * 1536 + col] = make_float2(c[nt][2], c[nt][3]);
    }
}

// ---------------- K0b: const tables ----------------
// B2: n=j', j'=2q -> W_pos row q (cos weights), j'=2q+1 -> row q+31 (sin); q=31 pad 0.
// B3: n=m, k=j, j=2q -> cos(a_{q+1} m), j=2q+1 -> sin(a_{q+1} m); q=31 pad 0.
// rot[l][q] = (cos(a_{q+1} l), sin(a_{q+1} l)) / 62; q=31 -> 0.
__global__ __launch_bounds__(256) void k_const(const float* __restrict__ W_pos) {
    int i = blockIdx.x * 256 + threadIdx.x;
    const float W0 = 6.283185307179586f / 63.0f;
    if (i < 1024) {
        int n = i >> 4, k0 = (i & 15) * 4;
        int q = n >> 1, p = (n & 1) ? q + 31 : q;
        float4 v = make_float4(0.f, 0.f, 0.f, 0.f);
        if (q < 31) v = *(const float4*)&W_pos[p * 64 + k0];
        b_store4n(g_B2h, g_B2l, n, k0, v);
    } else if (i < 2048) {
        int ii = i - 1024;
        int m = ii >> 4, r4 = ii & 15;
        int q0 = 2 * r4, q1 = 2 * r4 + 1;
        float4 v;
        float s, c;
        if (q0 < 31) { sincosf((float)(q0 + 1) * (float)m * W0, &s, &c); v.x = c; v.y = s; }
        else { v.x = 0.f; v.y = 0.f; }
        if (q1 < 31) { sincosf((float)(q1 + 1) * (float)m * W0, &s, &c); v.z = c; v.w = s; }
        else { v.z = 0.f; v.w = 0.f; }
        b_store4n(g_B3h, g_B3l, m, 4 * r4, v);
    } else if (i < 4096) {
        int ii = i - 2048;
        int l = ii >> 5, q = ii & 31;
        float2 r = make_float2(0.f, 0.f);
        if (q < 31) {
            float s, c;
            sincosf((float)(q + 1) * (float)l * W0, &s, &c);
            r = make_float2(c * (1.0f / 62.0f), s * (1.0f / 62.0f));
        }
        g_rotc[ii] = r;
    }
}

// ---------------- K1: fused attention: sim -> pos bias -> softmax -> AV -> LN ----------------
__global__ __launch_bounds__(128) void k_attn(const int* __restrict__ inputs,
                                              const float* __restrict__ ln_g,
                                              const float* __restrict__ ln_b) {
    __shared__ u32 QAH[2048], QAL[2048], KBH[2048], KBL[2048], VBH[2048], VBL[2048];
    int h = blockIdx.x, b = blockIdx.y, t = threadIdx.x;
    // fills: gather Q (A-frag), K (B-frag n-major), V (B-frag k-major)
    for (int i = t; i < 1024; i += 128) {
        int row = i >> 4, k0 = (i & 15) * 4;
        int tok = inputs[b * 64 + row];
        size_t base = (size_t)tok * 1536 + h * 64 + k0;
        a_store4(QAH, QAL, row, k0, *(const float4*)&g_qkv[base]);
        b_store4n(KBH, KBL, row, k0, *(const float4*)&g_qkv[base + 512]);
    }
    for (int i = t; i < 512; i += 128) {
        int kp = i >> 4, d0 = (i & 15) * 4;
        int te = inputs[b * 64 + 2 * kp], to = inputs[b * 64 + 2 * kp + 1];
        float4 ev = *(const float4*)&g_qkv[(size_t)te * 1536 + 1024 + h * 64 + d0];
        float4 od = *(const float4*)&g_qkv[(size_t)to * 1536 + 1024 + h * 64 + d0];
        b_store4k(VBH, VBL, 2 * kp, d0, ev, od);
    }
    __syncthreads();
    int lane = t & 31, w = t >> 5, grp = lane >> 2, tig = lane & 3;
    int l1 = 16 * w + grp, l2 = l1 + 8;

    // GEMM1: sim = Q @ K^T
    float cs[8][4] = {};
    MMA_GEMM(cs, QAH, QAL, KBH, KBL, w, lane);

    // scale, mask (z init in cs), clip (sc)
    float sc[8][4];
#pragma unroll
    for (int nt = 0; nt < 8; nt++) {
        int col = 8 * nt + 2 * tig;
        int m0 = (inputs[b * 64 + col] == 0);
        int m1 = (inputs[b * 64 + col + 1] == 0);
#pragma unroll
        for (int v = 0; v < 4; v++) {
            float s = cs[nt][v] * 0.125f;
            int mv = (v & 1) ? m1 : m0;
            sc[nt][v] = mv ? 0.f : s;
            cs[nt][v] = mv ? -1e9f : s;
        }
    }

    // GEMM2: posw = sclip @ B2 (W_pos interleaved cos/sin columns)
    float cpw[8][4] = {};
#pragma unroll
    for (int ks = 0; ks < 4; ks++) {
        u32 ah[4], al[4];
        c2a(sc[2 * ks], sc[2 * ks + 1], ah, al);
#pragma unroll
        for (int nt = 0; nt < 8; nt++) {
            int bi = ((ks * 8 + nt) * 32 + lane) * 2;
            uint2 bh = *(const uint2*)&g_B2h[bi];
            uint2 bl = *(const uint2*)&g_B2l[bi];
            mma_bf16(cpw[nt], ah, (const u32*)&bh);
            mma_bf16(cpw[nt], ah, (const u32*)&bl);
            mma_bf16(cpw[nt], al, (const u32*)&bh);
        }
    }

    // rotate: (u_c, u_s) -> (vc, vs) with per-(l,q) factors
#pragma unroll
    for (int nt = 0; nt < 8; nt++) {
        int q = 4 * nt + tig;
        float2 r1 = g_rotc[l1 * 32 + q];
        float2 r2 = g_rotc[l2 * 32 + q];
        float u0 = cpw[nt][0], u1 = cpw[nt][1];
        cpw[nt][0] = u0 * r1.x - u1 * r1.y;
        cpw[nt][1] = u0 * r1.y + u1 * r1.x;
        u0 = cpw[nt][2]; u1 = cpw[nt][3];
        cpw[nt][2] = u0 * r2.x - u1 * r2.y;
        cpw[nt][3] = u0 * r2.y + u1 * r2.x;
    }

    // GEMM3: z = sim_masked + rotated @ B3 (cos/sin basis)
#pragma unroll
    for (int ks = 0; ks < 4; ks++) {
        u32 ah[4], al[4];
        c2a(cpw[2 * ks], cpw[2 * ks + 1], ah, al);
#pragma unroll
        for (int nt = 0; nt < 8; nt++) {
            int bi = ((ks * 8 + nt) * 32 + lane) * 2;
            uint2 bh = *(const uint2*)&g_B3h[bi];
            uint2 bl = *(const uint2*)&g_B3l[bi];
            mma_bf16(cs[nt], ah, (const u32*)&bh);
            mma_bf16(cs[nt], ah, (const u32*)&bl);
            mma_bf16(cs[nt], al, (const u32*)&bh);
        }
    }

    // softmax on cs (two row-halves), probs back into cs
#pragma unroll
    for (int s = 0; s < 2; s++) {
        float mx = -3.4e38f;
#pragma unroll
        for (int nt = 0; nt < 8; nt++)
            mx = fmaxf(mx, fmaxf(cs[nt][2 * s], cs[nt][2 * s + 1]));
        mx = fmaxf(mx, __shfl_xor_sync(0xffffffffu, mx, 1));
        mx = fmaxf(mx, __shfl_xor_sync(0xffffffffu, mx, 2));
        float sm = 0.f;
#pragma unroll
        for (int nt = 0; nt < 8; nt++) {
            cs[nt][2 * s] = __expf(cs[nt][2 * s] - mx);
            cs[nt][2 * s + 1] = __expf(cs[nt][2 * s + 1] - mx);
            sm += cs[nt][2 * s] + cs[nt][2 * s + 1];
        }
        sm += __shfl_xor_sync(0xffffffffu, sm, 1);
        sm += __shfl_xor_sync(0xffffffffu, sm, 2);
        float inv = 1.0f / sm;
#pragma unroll
        for (int nt = 0; nt < 8; nt++) {
            cs[nt][2 * s] *= inv;
            cs[nt][2 * s + 1] *= inv;
        }
    }

    // GEMM4: out = attn @ V
    float cav[8][4] = {};
#pragma unroll
    for (int ks = 0; ks < 4; ks++) {
        u32 ah[4], al[4];
        c2a(cs[2 * ks], cs[2 * ks + 1], ah, al);
#pragma unroll
        for (int nt = 0; nt < 8; nt++) {
            uint2 bh = *(const uint2*)&VBH[((ks * 8 + nt) * 32 + lane) * 2];
            uint2 bl = *(const uint2*)&VBL[((ks * 8 + nt) * 32 + lane) * 2];
            mma_bf16(cav[nt], ah, (const u32*)&bh);
            mma_bf16(cav[nt], ah, (const u32*)&bl);
            mma_bf16(cav[nt], al, (const u32*)&bh);
        }
    }

    // layernorm epilogue
    size_t lo = (size_t)(b * NH + h) * 4096;
#pragma unroll
    for (int s = 0; s < 2; s++) {
        float a[8][2];
#pragma unroll
        for (int nt = 0; nt < 8; nt++) { a[nt][0] = cav[nt][2 * s]; a[nt][1] = cav[nt][2 * s + 1]; }
        float sm = 0.f, sq = 0.f;
#pragma unroll
        for (int nt = 0; nt < 8; nt++) {
            sm += a[nt][0] + a[nt][1];
            sq += a[nt][0] * a[nt][0] + a[nt][1] * a[nt][1];
        }
#pragma unroll
        for (int d = 1; d < 4; d <<= 1) {
            sm += __shfl_xor_sync(0xffffffffu, sm, d);
            sq += __shfl_xor_sync(0xffffffffu, sq, d);
        }
        float mu = sm * (1.0f / 64.0f);
        float var = sq * (1.0f / 64.0f) - mu * mu;
        float inv = rsqrtf(var + 1e-5f);
        size_t rb = lo + (size_t)(l1 + 8 * s) * 64;
#pragma unroll
        for (int nt = 0; nt < 8; nt++) {
            int col = 8 * nt + 2 * tig;
            float2 v;
            v.x = (a[nt][0] - mu) * inv * ln_g[col] + ln_b[col];
            v.y = (a[nt][1] - mu) * inv * ln_g[col + 1] + ln_b[col + 1];
            *(float2*)&g_ln[rb + col] = v;
        }
    }
}

// ---------------- K4: MLP + masked word mean, f32x2 o-pairs (unchanged) ----------------
__global__ __launch_bounds__(256, 3) void k_mlp(const int* __restrict__ inputs,
                                                const float* __restrict__ W1,
                                                const float* __restrict__ b1,
                                                const float* __restrict__ W2,
                                                const float* __restrict__ b2) {
    __shared__ u64 W1p[8][32];
    __shared__ float b1s[64];
    __shared__ float W2t[64][32];
    __shared__ float b2s[32];
    __shared__ float part[4][64][33];
    __shared__ int toks[64];
    int b = blockIdx.x, t = threadIdx.x;
    if (t < 64) { toks[t] = inputs[b * 64 + t]; b1s[t] = b1[t]; }
    if (t < 32) b2s[t] = b2[t];
    {
        int op = t & 31, hh = t >> 5;
        if (t < 256) W1p[hh][op] = pk2(W1[(2 * op) * 8 + hh], W1[(2 * op + 1) * 8 + hh]);
    }
    for (int i = t; i < 2048; i += 256) {
        int o = i >> 5, p = i & 31;
        W2t[o][p] = W2[p * 64 + o];
    }
    __syncthreads();
    float cnt = 0.f;
    for (int m = 0; m < 64; m++) cnt += (toks[m] != 0) ? 1.f : 0.f;

    int d = t & 63, lg = t >> 6;
    u64 acc2[16];
#pragma unroll
    for (int q = 0; q < 16; q++) acc2[q] = 0ull;
#pragma unroll 1
    for (int oc = 0; oc < 4; oc++) {
        float hs[16];
#pragma unroll
        for (int o2 = 0; o2 < 16; o2++) hs[o2] = 0.f;
        for (int li = 0; li < 16; li++) {
            int l = lg * 16 + li;
            if (toks[l] == 0) continue;
            u64 ftd[8];
#pragma unroll
            for (int hh = 0; hh < 8; hh++) {
                float f = g_ln[(((size_t)b * 8 + hh) * 64 + l) * 64 + d];
                ftd[hh] = pk2(f, f);
            }
#pragma unroll
            for (int pi = 0; pi < 8; pi++) {
                int opair = oc * 8 + pi;
                u64 v2 = *(const u64*)&b1s[2 * opair];
#pragma unroll
                for (int hh = 0; hh < 8; hh++)
                    fma2(v2, ftd[hh], W1p[hh][opair]);
                float2 vv = up2(v2);
                hs[2 * pi]     += fmaxf(vv.x, 0.f);
                hs[2 * pi + 1] += fmaxf(vv.y, 0.f);
            }
        }
#pragma unroll
        for (int o2 = 0; o2 < 16; o2++) {
            int o = oc * 16 + o2;
            u64 hv2 = pk2(hs[o2], hs[o2]);
#pragma unroll
            for (int q = 0; q < 16; q++)
                fma2(acc2[q], hv2, *(const u64*)&W2t[o][2 * q]);
        }
    }
#pragma unroll
    for (int q = 0; q < 16; q++) {
        float2 v = up2(acc2[q]);
        part[lg][d][2 * q] = v.x;
        part[lg][d][2 * q + 1] = v.y;
    }
    __syncthreads();
    float invc = 1.0f / cnt;
    for (int f = t; f < 2048; f += 256) {
        int dd = f >> 5, p = f & 31;
        float w = part[0][dd][p] + part[1][dd][p] + part[2][dd][p] + part[3][dd][p];
        g_word[(size_t)b * 2048 + f] = w * invc + b2s[p];
    }
}

// ---------------- K5: name mean over n_words ----------------
__global__ __launch_bounds__(256) void k_name(float* __restrict__ out, int n_words, int total) {
    int idx = blockIdx.x * 256 + threadIdx.x;
    if (idx >= total) return;
    int g = idx >> 11, f = idx & 2047;
    float s = 0.f;
    for (int w = 0; w < n_words; w++)
        s += g_word[(size_t)(g * n_words + w) * 2048 + f];
    out[idx] = s / (float)n_words;
}

// ---------------- launch ----------------
extern "C" void kernel_launch(void* const* d_in, const int* in_sizes, int n_in,
                              void* d_out, int out_size) {
    const int* inputs  = (const int*)d_in[0];
    const float* W_emb = (const float*)d_in[1];
    const float* W_qkv = (const float*)d_in[2];
    const float* W_pos = (const float*)d_in[3];
    const float* ln_g  = (const float*)d_in[4];
    const float* ln_b  = (const float*)d_in[5];
    const float* W1    = (const float*)d_in[6];
    const float* b1    = (const float*)d_in[7];
    const float* W2    = (const float*)d_in[8];
    const float* b2    = (const float*)d_in[9];

    int B = in_sizes[0] / 64;                         // 2048
    int V = in_sizes[1] / 64;                         // 4096
    int n_words = (int)(((long long)B * 2048) / out_size);

    k_qkv<<<dim3(24, V / 64), 128>>>(W_emb, W_qkv);
    k_const<<<16, 256>>>(W_pos);
    k_attn<<<dim3(NH, B), 128>>>(inputs, ln_g, ln_b);
    k_mlp<<<B, 256>>>(inputs, W1, b1, W2, b2);
    k_name<<<(out_size + 255) / 256, 256>>>((float*)d_out, n_words, out_size);
}